// round 2
// baseline (speedup 1.0000x reference)
#include <cuda_runtime.h>
#include <cuda_bf16.h>
#include <stdint.h>

// ---------------------------------------------------------------------------
// Problem dims (from reference): N=50000, D=128, GCN out=512, H=256, E=800000
// edge_index is int32 (JAX x64 disabled downgrades jnp.int64 -> int32).
// ---------------------------------------------------------------------------
#define MAXN 50000
#define MAXE 800000
#define DGCN 512
#define HDIM 256

// Scratch (device globals; allocation-free per harness rules)
__device__ float g_h[(size_t)MAXN * DGCN];     // x @ W_gcn            [N,512]
__device__ float g_agg[(size_t)MAXN * DGCN];   // gcn_conv output      [N,512]
__device__ float g_h1[(size_t)MAXN * HDIM];    // mlp hidden 1 (and 3) [N,256]
__device__ float g_h2[(size_t)MAXN * HDIM];    // mlp hidden 2         [N,256]
__device__ float g_deg[MAXN];
__device__ float g_dinv[MAXN];

#define DIV_UP(a, b) (((a) + (b) - 1) / (b))

__device__ __forceinline__ float leaky(float v) { return v > 0.f ? v : 0.1f * v; }

// ---------------------------------------------------------------------------
// Tiled SGEMM: C[M,N] = A[M,K] @ B[K,N] (+bias) (+leakyReLU)
// BM=BN=64, BK=16, TM=TN=4, 256 threads. Requires N%64==0, K%16==0, 16B-aligned.
// ---------------------------------------------------------------------------
template <bool BIAS, bool LEAKY>
__global__ void sgemm_kernel(const float* __restrict__ A,
                             const float* __restrict__ B,
                             const float* __restrict__ bias,
                             float* __restrict__ C,
                             int M, int N, int K) {
    constexpr int BM = 64, BN = 64, BK = 16, TM = 4, TN = 4;
    __shared__ float As[BK][BM];
    __shared__ float Bs[BK][BN];

    const int tid = threadIdx.x;
    const int block_row = blockIdx.y * BM;
    const int block_col = blockIdx.x * BN;

    const int tcol = tid % (BN / TN);   // 0..15
    const int trow = tid / (BN / TN);   // 0..15

    // A-tile load mapping: each thread one float4 (BM*BK = 1024 floats / 256 thr)
    const int a_row = tid / (BK / 4);        // 0..63
    const int a_col = (tid % (BK / 4)) * 4;  // 0,4,8,12
    // B-tile load mapping: each thread one float4 (BK*BN = 1024 floats)
    const int b_row = tid / (BN / 4);        // 0..15
    const int b_col = (tid % (BN / 4)) * 4;  // 0..60

    float acc[TM][TN] = {};

    for (int k0 = 0; k0 < K; k0 += BK) {
        float4 av = make_float4(0.f, 0.f, 0.f, 0.f);
        const int gr = block_row + a_row;
        if (gr < M)
            av = *reinterpret_cast<const float4*>(&A[(size_t)gr * K + k0 + a_col]);
        As[a_col + 0][a_row] = av.x;
        As[a_col + 1][a_row] = av.y;
        As[a_col + 2][a_row] = av.z;
        As[a_col + 3][a_row] = av.w;

        const float4 bv = *reinterpret_cast<const float4*>(
            &B[(size_t)(k0 + b_row) * N + block_col + b_col]);
        *reinterpret_cast<float4*>(&Bs[b_row][b_col]) = bv;

        __syncthreads();

#pragma unroll
        for (int k = 0; k < BK; ++k) {
            const float4 am = *reinterpret_cast<const float4*>(&As[k][trow * TM]);
            const float4 bn = *reinterpret_cast<const float4*>(&Bs[k][tcol * TN]);
            const float a0 = am.x, a1 = am.y, a2 = am.z, a3 = am.w;
            const float b0 = bn.x, b1 = bn.y, b2 = bn.z, b3 = bn.w;
            acc[0][0] += a0 * b0; acc[0][1] += a0 * b1; acc[0][2] += a0 * b2; acc[0][3] += a0 * b3;
            acc[1][0] += a1 * b0; acc[1][1] += a1 * b1; acc[1][2] += a1 * b2; acc[1][3] += a1 * b3;
            acc[2][0] += a2 * b0; acc[2][1] += a2 * b1; acc[2][2] += a2 * b2; acc[2][3] += a2 * b3;
            acc[3][0] += a3 * b0; acc[3][1] += a3 * b1; acc[3][2] += a3 * b2; acc[3][3] += a3 * b3;
        }
        __syncthreads();
    }

#pragma unroll
    for (int i = 0; i < TM; ++i) {
        const int r = block_row + trow * TM + i;
        if (r >= M) continue;
        const int c = block_col + tcol * TN;
        float4 v = make_float4(acc[i][0], acc[i][1], acc[i][2], acc[i][3]);
        if (BIAS) {
            v.x += bias[c + 0]; v.y += bias[c + 1];
            v.z += bias[c + 2]; v.w += bias[c + 3];
        }
        if (LEAKY) {
            v.x = leaky(v.x); v.y = leaky(v.y); v.z = leaky(v.z); v.w = leaky(v.w);
        }
        *reinterpret_cast<float4*>(&C[(size_t)r * N + c]) = v;
    }
}

// ---------------------------------------------------------------------------
// Degree / norm kernels
// ---------------------------------------------------------------------------
__global__ void deg_init_kernel(int n) {
    int i = blockIdx.x * blockDim.x + threadIdx.x;
    if (i < n) g_deg[i] = 1.0f;  // self loop
}

__global__ void deg_count_kernel(const int* __restrict__ dst, int E, int n) {
    int e = blockIdx.x * blockDim.x + threadIdx.x;
    if (e < E) {
        int d = dst[e];
        if (d >= 0 && d < n) atomicAdd(&g_deg[d], 1.0f);
    }
}

__global__ void dinv_kernel(int n) {
    int i = blockIdx.x * blockDim.x + threadIdx.x;
    if (i < n) g_dinv[i] = rsqrtf(g_deg[i]);   // deg >= 1 always
}

// agg[i][c] = h[i][c] * dinv[i]^2 + b_gcn[c]   (self-loop term + bias)
__global__ void agg_init_kernel(const float* __restrict__ b_gcn, int n) {
    const size_t total = (size_t)n * (DGCN / 4);
    size_t t = (size_t)blockIdx.x * blockDim.x + threadIdx.x;
    if (t >= total) return;
    const int node = (int)(t >> 7);   // 512/4 = 128 float4 per node
    const int c4 = (int)(t & 127);
    const float di = g_dinv[node];
    const float w = di * di;
    const float4 h4 = reinterpret_cast<const float4*>(g_h)[t];
    const float4 b4 = reinterpret_cast<const float4*>(b_gcn)[c4];
    float4 o;
    o.x = h4.x * w + b4.x;
    o.y = h4.y * w + b4.y;
    o.z = h4.z * w + b4.z;
    o.w = h4.w * w + b4.w;
    reinterpret_cast<float4*>(g_agg)[t] = o;
}

// One edge handled by 128 threads (float4 each => 512 cols). 2 edges per block.
__global__ void edge_scatter_kernel(const int* __restrict__ src,
                                    const int* __restrict__ dst, int E, int n) {
    const int e = blockIdx.x * 2 + (threadIdx.x >> 7);
    if (e >= E) return;
    const int lane = threadIdx.x & 127;
    const int s = src[e];
    const int d = dst[e];
    if ((unsigned)s >= (unsigned)n || (unsigned)d >= (unsigned)n) return;
    const float nrm = g_dinv[s] * g_dinv[d];
    const float4 v = reinterpret_cast<const float4*>(g_h)[(size_t)s * 128 + lane];
    float* out = &g_agg[(size_t)d * DGCN + lane * 4];
    atomicAdd(out + 0, v.x * nrm);
    atomicAdd(out + 1, v.y * nrm);
    atomicAdd(out + 2, v.z * nrm);
    atomicAdd(out + 3, v.w * nrm);
}

// ---------------------------------------------------------------------------
// Final: out[i] = h3[i,:] . W_out + b_out   (one warp per row)
// ---------------------------------------------------------------------------
__global__ void final_dot_kernel(const float* __restrict__ Wout,
                                 const float* __restrict__ bout,
                                 float* __restrict__ out, int n) {
    const int warp = (blockIdx.x * blockDim.x + threadIdx.x) >> 5;
    const int lane = threadIdx.x & 31;
    if (warp >= n) return;
    const float* row = &g_h1[(size_t)warp * HDIM];  // h3 lives in g_h1
    float s = 0.f;
#pragma unroll
    for (int i = 0; i < 8; ++i)
        s += row[lane + 32 * i] * Wout[lane + 32 * i];
#pragma unroll
    for (int o = 16; o; o >>= 1) s += __shfl_xor_sync(0xFFFFFFFFu, s, o);
    if (lane == 0) out[warp] = s + bout[0];
}

// ---------------------------------------------------------------------------
// Launch
// ---------------------------------------------------------------------------
extern "C" void kernel_launch(void* const* d_in, const int* in_sizes, int n_in,
                              void* d_out, int out_size) {
    const float* x      = (const float*)d_in[0];
    const int*   ei     = (const int*)d_in[1];      // int32 edge_index [2,E]
    const float* W_gcn  = (const float*)d_in[2];
    const float* b_gcn  = (const float*)d_in[3];
    const float* W1     = (const float*)d_in[4];
    const float* b1     = (const float*)d_in[5];
    const float* W2     = (const float*)d_in[6];
    const float* b2     = (const float*)d_in[7];
    const float* W3     = (const float*)d_in[8];
    const float* b3     = (const float*)d_in[9];
    const float* Wout   = (const float*)d_in[10];
    const float* bout   = (const float*)d_in[11];
    float* out = (float*)d_out;

    const int N = in_sizes[0] / 128;
    const int E = in_sizes[1] / 2;
    const int* src = ei;
    const int* dst = ei + E;

    float *p_h, *p_agg, *p_h1, *p_h2;
    cudaGetSymbolAddress((void**)&p_h, g_h);
    cudaGetSymbolAddress((void**)&p_agg, g_agg);
    cudaGetSymbolAddress((void**)&p_h1, g_h1);
    cudaGetSymbolAddress((void**)&p_h2, g_h2);

    // 1) h = x @ W_gcn    [N,128]x[128,512]
    {
        dim3 grid(DGCN / 64, DIV_UP(N, 64));
        sgemm_kernel<false, false><<<grid, 256>>>(x, W_gcn, nullptr, p_h, N, DGCN, 128);
    }

    // 2) degrees + norms
    deg_init_kernel<<<DIV_UP(N, 256), 256>>>(N);
    deg_count_kernel<<<DIV_UP(E, 256), 256>>>(dst, E, N);
    dinv_kernel<<<DIV_UP(N, 256), 256>>>(N);

    // 3) agg = selfloop + bias, then scatter edges
    agg_init_kernel<<<DIV_UP(N * (DGCN / 4), 256), 256>>>(b_gcn, N);
    edge_scatter_kernel<<<DIV_UP(E, 2), 256>>>(src, dst, E, N);

    // 4) MLP
    {
        dim3 grid(HDIM / 64, DIV_UP(N, 64));
        sgemm_kernel<true, true><<<grid, 256>>>(p_agg, W1, b1, p_h1, N, HDIM, DGCN);
        sgemm_kernel<true, true><<<grid, 256>>>(p_h1, W2, b2, p_h2, N, HDIM, HDIM);
        sgemm_kernel<true, true><<<grid, 256>>>(p_h2, W3, b3, p_h1, N, HDIM, HDIM);
    }

    // 5) final dot -> [N,1]
    final_dot_kernel<<<DIV_UP(N * 32, 256), 256>>>(Wout, bout, out, N);
}

// round 4
// speedup vs baseline: 2.2302x; 2.2302x over previous
#include <cuda_runtime.h>
#include <cuda_bf16.h>
#include <stdint.h>

// ---------------------------------------------------------------------------
// N=50000, D=128, GCN out=512, H=256, E=800000. edge_index int32.
//
// Restructure: gcn_conv(x) = (S @ x) @ W_gcn + b, where S is normalized adj.
// Aggregate in 128-dim x-space (4x less traffic), CSR-sorted (no f32 atomics).
// ---------------------------------------------------------------------------
#define MAXN 50000
#define MAXE 800000
#define DIN  128
#define DGCN 512
#define HDIM 256

__device__ float g_xs[(size_t)MAXN * DIN];     // S @ x                [N,128]
__device__ float g_agg[(size_t)MAXN * DGCN];   // gcn output           [N,512]
__device__ float g_h1[(size_t)MAXN * HDIM];
__device__ float g_h2[(size_t)MAXN * HDIM];
__device__ float g_dinv[MAXN];
__device__ int   g_cnt[MAXN];
__device__ int   g_start[MAXN];
__device__ int   g_cursor[MAXN];
__device__ int   g_csrc[MAXE];

#define DIV_UP(a, b) (((a) + (b) - 1) / (b))

__device__ __forceinline__ float leaky(float v) { return v > 0.f ? v : 0.1f * v; }

// ---------------------------------------------------------------------------
// SGEMM 128x128 tile, BK=16, 256 threads, 8x8 microtile (4+4 split halves).
// Requires N%128==0, K%16==0. M guarded.
// ---------------------------------------------------------------------------
template <bool BIAS, bool LEAKY>
__global__ __launch_bounds__(256, 2)
void sgemm128(const float* __restrict__ A, const float* __restrict__ B,
              const float* __restrict__ bias, float* __restrict__ C,
              int M, int N, int K) {
    __shared__ float As[16][128];
    __shared__ float Bs[16][128];

    const int tid = threadIdx.x;
    const int brow = blockIdx.y * 128;
    const int bcol = blockIdx.x * 128;
    const int trow = tid / 16;          // 0..15
    const int tcol = tid % 16;          // 0..15

    const int ar = tid / 4;             // 0..63  (A rows ar, ar+64)
    const int ac = (tid % 4) * 4;       // 0,4,8,12
    const int br = tid / 32;            // 0..7   (B rows br, br+8)
    const int bc = (tid % 32) * 4;      // 0..124

    float acc[2][2][4][4] = {};

    for (int k0 = 0; k0 < K; k0 += 16) {
#pragma unroll
        for (int h = 0; h < 2; ++h) {
            const int r = brow + ar + h * 64;
            float4 v = make_float4(0.f, 0.f, 0.f, 0.f);
            if (r < M) v = *reinterpret_cast<const float4*>(&A[(size_t)r * K + k0 + ac]);
            As[ac + 0][ar + h * 64] = v.x;
            As[ac + 1][ar + h * 64] = v.y;
            As[ac + 2][ar + h * 64] = v.z;
            As[ac + 3][ar + h * 64] = v.w;
        }
#pragma unroll
        for (int h = 0; h < 2; ++h) {
            *reinterpret_cast<float4*>(&Bs[br + h * 8][bc]) =
                *reinterpret_cast<const float4*>(&B[(size_t)(k0 + br + h * 8) * N + bcol + bc]);
        }
        __syncthreads();

#pragma unroll
        for (int k = 0; k < 16; ++k) {
            float a[2][4], b[2][4];
            *reinterpret_cast<float4*>(a[0]) = *reinterpret_cast<const float4*>(&As[k][trow * 4]);
            *reinterpret_cast<float4*>(a[1]) = *reinterpret_cast<const float4*>(&As[k][64 + trow * 4]);
            *reinterpret_cast<float4*>(b[0]) = *reinterpret_cast<const float4*>(&Bs[k][tcol * 4]);
            *reinterpret_cast<float4*>(b[1]) = *reinterpret_cast<const float4*>(&Bs[k][64 + tcol * 4]);
#pragma unroll
            for (int i = 0; i < 2; ++i)
#pragma unroll
                for (int j = 0; j < 2; ++j)
#pragma unroll
                    for (int m = 0; m < 4; ++m)
#pragma unroll
                        for (int n = 0; n < 4; ++n)
                            acc[i][j][m][n] += a[i][m] * b[j][n];
        }
        __syncthreads();
    }

#pragma unroll
    for (int i = 0; i < 2; ++i) {
#pragma unroll
        for (int m = 0; m < 4; ++m) {
            const int r = brow + i * 64 + trow * 4 + m;
            if (r >= M) continue;
#pragma unroll
            for (int j = 0; j < 2; ++j) {
                const int c = bcol + j * 64 + tcol * 4;
                float4 v = make_float4(acc[i][j][m][0], acc[i][j][m][1],
                                       acc[i][j][m][2], acc[i][j][m][3]);
                if (BIAS) {
                    const float4 bb = *reinterpret_cast<const float4*>(&bias[c]);
                    v.x += bb.x; v.y += bb.y; v.z += bb.z; v.w += bb.w;
                }
                if (LEAKY) {
                    v.x = leaky(v.x); v.y = leaky(v.y);
                    v.z = leaky(v.z); v.w = leaky(v.w);
                }
                *reinterpret_cast<float4*>(&C[(size_t)r * N + c]) = v;
            }
        }
    }
}

// ---------------------------------------------------------------------------
// CSR build
// ---------------------------------------------------------------------------
__global__ void zero_kernel(int n) {
    int i = blockIdx.x * blockDim.x + threadIdx.x;
    if (i < n) { g_cnt[i] = 0; g_cursor[i] = 0; }
}

__global__ void hist_kernel(const int* __restrict__ dst, int E, int n) {
    int e = blockIdx.x * blockDim.x + threadIdx.x;
    if (e < E) {
        int d = dst[e];
        if ((unsigned)d < (unsigned)n) atomicAdd(&g_cnt[d], 1);
    }
}

__global__ void dinv_kernel(int n) {
    int i = blockIdx.x * blockDim.x + threadIdx.x;
    if (i < n) g_dinv[i] = rsqrtf(1.0f + (float)g_cnt[i]);
}

// Single-block exclusive scan of g_cnt -> g_start (1024 threads, chunked).
__global__ void scan_kernel(int n) {
    __shared__ int part[1024];
    const int t = threadIdx.x;
    const int chunk = DIV_UP(n, 1024);
    const int lo = t * chunk;
    const int hi = min(lo + chunk, n);
    int s = 0;
    for (int i = lo; i < hi; ++i) s += g_cnt[i];
    part[t] = s;
    __syncthreads();
    for (int off = 1; off < 1024; off <<= 1) {
        int v = (t >= off) ? part[t - off] : 0;
        __syncthreads();
        part[t] += v;
        __syncthreads();
    }
    int run = (t == 0) ? 0 : part[t - 1];
    for (int i = lo; i < hi; ++i) { g_start[i] = run; run += g_cnt[i]; }
}

__global__ void scatter_kernel(const int* __restrict__ src,
                               const int* __restrict__ dst, int E, int n) {
    int e = blockIdx.x * blockDim.x + threadIdx.x;
    if (e < E) {
        int d = dst[e];
        int s = src[e];
        if ((unsigned)d >= (unsigned)n || (unsigned)s >= (unsigned)n) return;
        int pos = g_start[d] + atomicAdd(&g_cursor[d], 1);
        g_csrc[pos] = s;
    }
}

// ---------------------------------------------------------------------------
// Aggregation in 128-dim: xs[n] = dinv[n] * (dinv[n]*x[n] + sum dinv[s]*x[s])
// One block of 128 threads per node; thread = one column.
// ---------------------------------------------------------------------------
__global__ __launch_bounds__(128)
void agg128_kernel(const float* __restrict__ x, int n) {
    const int node = blockIdx.x;
    const int c = threadIdx.x;
    const float di = g_dinv[node];
    float acc = di * x[(size_t)node * DIN + c];
    const int lo = g_start[node];
    const int hi = lo + g_cnt[node];
    for (int j = lo; j < hi; ++j) {
        const int s = g_csrc[j];
        acc += g_dinv[s] * x[(size_t)s * DIN + c];
    }
    g_xs[(size_t)node * DIN + c] = di * acc;
}

// ---------------------------------------------------------------------------
// Final: out[i] = h3[i,:] . W_out + b_out   (one warp per row)
// ---------------------------------------------------------------------------
__global__ void final_dot_kernel(const float* __restrict__ Wout,
                                 const float* __restrict__ bout,
                                 float* __restrict__ out, int n) {
    const int warp = (blockIdx.x * blockDim.x + threadIdx.x) >> 5;
    const int lane = threadIdx.x & 31;
    if (warp >= n) return;
    const float* row = &g_h1[(size_t)warp * HDIM];  // h3 lives in g_h1
    float s = 0.f;
#pragma unroll
    for (int i = 0; i < 8; ++i)
        s += row[lane + 32 * i] * Wout[lane + 32 * i];
#pragma unroll
    for (int o = 16; o; o >>= 1) s += __shfl_xor_sync(0xFFFFFFFFu, s, o);
    if (lane == 0) out[warp] = s + bout[0];
}

// ---------------------------------------------------------------------------
// Launch
// ---------------------------------------------------------------------------
extern "C" void kernel_launch(void* const* d_in, const int* in_sizes, int n_in,
                              void* d_out, int out_size) {
    const float* x      = (const float*)d_in[0];
    const int*   ei     = (const int*)d_in[1];
    const float* W_gcn  = (const float*)d_in[2];
    const float* b_gcn  = (const float*)d_in[3];
    const float* W1     = (const float*)d_in[4];
    const float* b1     = (const float*)d_in[5];
    const float* W2     = (const float*)d_in[6];
    const float* b2     = (const float*)d_in[7];
    const float* W3     = (const float*)d_in[8];
    const float* b3     = (const float*)d_in[9];
    const float* Wout   = (const float*)d_in[10];
    const float* bout   = (const float*)d_in[11];
    float* out = (float*)d_out;

    const int N = in_sizes[0] / DIN;
    const int E = in_sizes[1] / 2;
    const int* src = ei;
    const int* dst = ei + E;

    float *p_xs, *p_agg, *p_h1, *p_h2;
    cudaGetSymbolAddress((void**)&p_xs, g_xs);
    cudaGetSymbolAddress((void**)&p_agg, g_agg);
    cudaGetSymbolAddress((void**)&p_h1, g_h1);
    cudaGetSymbolAddress((void**)&p_h2, g_h2);

    // CSR build + norms
    zero_kernel<<<DIV_UP(N, 256), 256>>>(N);
    hist_kernel<<<DIV_UP(E, 256), 256>>>(dst, E, N);
    dinv_kernel<<<DIV_UP(N, 256), 256>>>(N);
    scan_kernel<<<1, 1024>>>(N);
    scatter_kernel<<<DIV_UP(E, 256), 256>>>(src, dst, E, N);

    // xs = S @ x   [N,128]
    agg128_kernel<<<N, 128>>>(x, N);

    // agg = xs @ W_gcn + b_gcn   [N,512]
    {
        dim3 grid(DGCN / 128, DIV_UP(N, 128));
        sgemm128<true, false><<<grid, 256>>>(p_xs, W_gcn, b_gcn, p_agg, N, DGCN, DIN);
    }
    // MLP
    {
        dim3 grid(HDIM / 128, DIV_UP(N, 128));
        sgemm128<true, true><<<grid, 256>>>(p_agg, W1, b1, p_h1, N, HDIM, DGCN);
        sgemm128<true, true><<<grid, 256>>>(p_h1, W2, b2, p_h2, N, HDIM, HDIM);
        sgemm128<true, true><<<grid, 256>>>(p_h2, W3, b3, p_h1, N, HDIM, HDIM);
    }

    // out
    final_dot_kernel<<<DIV_UP(N * 32, 256), 256>>>(Wout, bout, out, N);
}

// round 6
// speedup vs baseline: 4.0272x; 1.8058x over previous
#include <cuda_runtime.h>
#include <cuda_bf16.h>
#include <stdint.h>

// ---------------------------------------------------------------------------
// N=50000, D=128, GCN out=512, H=256, E=800000. edge_index int32.
// gcn_conv(x) = (S @ x) @ W_gcn + b  (aggregate in 128-dim x-space, CSR).
// GEMMs: warp-level mma.sync bf16 (sm_100 base target; tcgen05 unavailable
// because harness compiles for sm_100, not sm_100a) with 3-term hi/lo split.
// ---------------------------------------------------------------------------
#define MAXN  50000
#define MAXNP 50048      // multiple of 128; padded rows are zero
#define MAXE  800000
#define DIN   128
#define DGCN  512
#define HDIM  256
#define DIV_UP(a, b) (((a) + (b) - 1) / (b))

typedef __nv_bfloat16 bf16;

// ---- scratch (device globals; zero-initialized at module load) ----
__device__ bf16  g_xs_h[(size_t)MAXNP * DIN],  g_xs_l[(size_t)MAXNP * DIN];
__device__ bf16  g_ag_h[(size_t)MAXNP * DGCN], g_ag_l[(size_t)MAXNP * DGCN];
__device__ bf16  g_h1_h[(size_t)MAXNP * HDIM], g_h1_l[(size_t)MAXNP * HDIM];
__device__ bf16  g_h2_h[(size_t)MAXNP * HDIM], g_h2_l[(size_t)MAXNP * HDIM];
__device__ float g_h3[(size_t)MAXNP * HDIM];
// transposed + split weights  [NOUT, K]
__device__ bf16 g_Wg_h[DGCN * DIN],  g_Wg_l[DGCN * DIN];
__device__ bf16 g_W1_h[HDIM * DGCN], g_W1_l[HDIM * DGCN];
__device__ bf16 g_W2_h[HDIM * HDIM], g_W2_l[HDIM * HDIM];
__device__ bf16 g_W3_h[HDIM * HDIM], g_W3_l[HDIM * HDIM];
// graph
__device__ float g_dinv[MAXN];
__device__ int   g_cnt[MAXN], g_start[MAXN], g_cursor[MAXN], g_csrc[MAXE];
__device__ int   g_blk[256];

__device__ __forceinline__ float leaky(float v) { return v > 0.f ? v : 0.1f * v; }

__device__ __forceinline__ uint32_t smem_u32(const void* p) {
    uint32_t a;
    asm("{ .reg .u64 t; cvta.to.shared.u64 t, %1; cvt.u32.u64 %0, t; }"
        : "=r"(a) : "l"(p));
    return a;
}

// smem tile: 128 rows x 64 bytes (32 bf16); chunk = 16B; swizzle keeps
// ldmatrix 8-lane phases and cp.async writes conflict-free.
__device__ __forceinline__ uint32_t swz(int row, int chunk) {
    return (uint32_t)(row * 64 + ((chunk ^ ((row ^ (row >> 2)) & 3)) * 16));
}

// ---------------------------------------------------------------------------
// bf16x3 warp-MMA GEMM: C[M,NOUT] = split(A[M,K]) @ split(B[NOUT,K])^T
// Block 128x128, BK=32, 256 thr (8 warps, 2x4), warp tile 64x32.
// A/C buffers are padded to a multiple of 128 rows -> no bounds guards.
// ---------------------------------------------------------------------------
template <int K, bool LEAKY, bool F32OUT>
__global__ __launch_bounds__(256)
void mma_gemm(const bf16* __restrict__ Ah, const bf16* __restrict__ Al,
              const bf16* __restrict__ Bh, const bf16* __restrict__ Bl,
              const float* __restrict__ bias,
              bf16* __restrict__ Ch, bf16* __restrict__ Cl,
              float* __restrict__ Cf, int NOUT) {
    extern __shared__ char sm[];
    const uint32_t sbase = smem_u32(sm);

    const int tid = threadIdx.x;
    const int lane = tid & 31, wid = tid >> 5;
    const int wm = wid >> 2, wn = wid & 3;        // 2 x 4 warp grid
    const int brow = blockIdx.y * 128;
    const int bcol = blockIdx.x * 128;

    float acc[4][4][4] = {};
    constexpr int NST = K / 32;

    // ---- stage loader: Ah|Al|Bh|Bl tiles, 128x32 bf16 each (8KB) ----
    auto load_stage = [&](int s, int buf) {
        const int kofs = s * 32;
        const uint32_t sb = sbase + buf * 32768;
#pragma unroll
        for (int i = 0; i < 8; ++i) {
            const int g = tid + 256 * i;          // 0..2047
            const int tile = g >> 9;              // 512 chunks per tile
            const int idx = g & 511;
            const int row = idx >> 2, c = idx & 3;
            const bf16* src;
            if (tile == 0)      src = Ah + (size_t)(brow + row) * K + kofs + c * 8;
            else if (tile == 1) src = Al + (size_t)(brow + row) * K + kofs + c * 8;
            else if (tile == 2) src = Bh + (size_t)(bcol + row) * K + kofs + c * 8;
            else                src = Bl + (size_t)(bcol + row) * K + kofs + c * 8;
            const uint32_t dst = sb + tile * 8192 + swz(row, c);
            asm volatile("cp.async.cg.shared.global [%0], [%1], 16;"
                         :: "r"(dst), "l"(src));
        }
        asm volatile("cp.async.commit_group;" ::: "memory");
    };

    auto do_compute = [&](int buf) {
        const uint32_t sb = sbase + buf * 32768;
#pragma unroll
        for (int t = 0; t < 3; ++t) {             // Ah*Bh, Ah*Bl, Al*Bh
            const uint32_t Ab = sb + (t == 2 ? 8192 : 0);
            const uint32_t Bb = sb + 16384 + (t == 1 ? 8192 : 0);
#pragma unroll
            for (int ks = 0; ks < 2; ++ks) {      // two k16 steps per BK=32
                uint32_t a[4][4];
#pragma unroll
                for (int mi = 0; mi < 4; ++mi) {
                    const int row = wm * 64 + mi * 16 + (lane & 7) + ((lane >> 3) & 1) * 8;
                    const int ch = ks * 2 + (lane >> 4);
                    const uint32_t ad = Ab + swz(row, ch);
                    asm volatile(
                        "ldmatrix.sync.aligned.m8n8.x4.shared.b16 {%0,%1,%2,%3}, [%4];"
                        : "=r"(a[mi][0]), "=r"(a[mi][1]), "=r"(a[mi][2]), "=r"(a[mi][3])
                        : "r"(ad));
                }
                uint32_t b[4][2];
#pragma unroll
                for (int p = 0; p < 2; ++p) {
                    const int row = wn * 32 + p * 16 + ((lane >> 4) & 1) * 8 + (lane & 7);
                    const int ch = ks * 2 + ((lane >> 3) & 1);
                    const uint32_t bd = Bb + swz(row, ch);
                    uint32_t r0, r1, r2, r3;
                    asm volatile(
                        "ldmatrix.sync.aligned.m8n8.x4.shared.b16 {%0,%1,%2,%3}, [%4];"
                        : "=r"(r0), "=r"(r1), "=r"(r2), "=r"(r3) : "r"(bd));
                    b[p * 2][0] = r0; b[p * 2][1] = r1;
                    b[p * 2 + 1][0] = r2; b[p * 2 + 1][1] = r3;
                }
#pragma unroll
                for (int mi = 0; mi < 4; ++mi)
#pragma unroll
                    for (int ni = 0; ni < 4; ++ni)
                        asm volatile(
                            "mma.sync.aligned.m16n8k16.row.col.f32.bf16.bf16.f32 "
                            "{%0,%1,%2,%3}, {%4,%5,%6,%7}, {%8,%9}, {%0,%1,%2,%3};"
                            : "+f"(acc[mi][ni][0]), "+f"(acc[mi][ni][1]),
                              "+f"(acc[mi][ni][2]), "+f"(acc[mi][ni][3])
                            : "r"(a[mi][0]), "r"(a[mi][1]), "r"(a[mi][2]), "r"(a[mi][3]),
                              "r"(b[ni][0]), "r"(b[ni][1]));
            }
        }
    };

    load_stage(0, 0);
    for (int s = 0; s < NST; ++s) {
        asm volatile("cp.async.wait_group 0;" ::: "memory");
        __syncthreads();
        if (s + 1 < NST) load_stage(s + 1, (s + 1) & 1);
        do_compute(s & 1);
        __syncthreads();
    }

    // ---- epilogue: bias (+leaky) (+re-split to bf16 hi/lo) ----
#pragma unroll
    for (int mi = 0; mi < 4; ++mi) {
        const int r0 = brow + wm * 64 + mi * 16 + (lane >> 2);
#pragma unroll
        for (int ni = 0; ni < 4; ++ni) {
            const int col = bcol + wn * 32 + ni * 8 + (lane & 3) * 2;
            const float2 bb = *(const float2*)&bias[col];
#pragma unroll
            for (int h = 0; h < 2; ++h) {
                const int r = r0 + h * 8;
                float v0 = acc[mi][ni][h * 2 + 0] + bb.x;
                float v1 = acc[mi][ni][h * 2 + 1] + bb.y;
                if (LEAKY) { v0 = leaky(v0); v1 = leaky(v1); }
                if (F32OUT) {
                    *(float2*)&Cf[(size_t)r * NOUT + col] = make_float2(v0, v1);
                } else {
                    const __nv_bfloat162 hv = __floats2bfloat162_rn(v0, v1);
                    *(__nv_bfloat162*)&Ch[(size_t)r * NOUT + col] = hv;
                    const float l0 = v0 - __bfloat162float(hv.x);
                    const float l1 = v1 - __bfloat162float(hv.y);
                    *(__nv_bfloat162*)&Cl[(size_t)r * NOUT + col] =
                        __floats2bfloat162_rn(l0, l1);
                }
            }
        }
    }
}

// ---------------------------------------------------------------------------
// Weight prep: transpose [K,NOUT] -> [NOUT,K] and split hi/lo
// ---------------------------------------------------------------------------
__global__ void prep_w(const float* __restrict__ W, bf16* __restrict__ Th,
                       bf16* __restrict__ Tl, int K, int NOUT) {
    const int idx = blockIdx.x * blockDim.x + threadIdx.x;
    if (idx >= K * NOUT) return;
    const int n = idx / K, k = idx % K;
    const float v = W[(size_t)k * NOUT + n];
    const bf16 h = __float2bfloat16(v);
    Th[idx] = h;
    Tl[idx] = __float2bfloat16(v - __bfloat162float(h));
}

// ---------------------------------------------------------------------------
// CSR build
// ---------------------------------------------------------------------------
__global__ void zero_kernel(int n) {
    int i = blockIdx.x * blockDim.x + threadIdx.x;
    if (i < n) { g_cnt[i] = 0; g_cursor[i] = 0; }
}
__global__ void hist_kernel(const int* __restrict__ dst, int E, int n) {
    int e = blockIdx.x * blockDim.x + threadIdx.x;
    if (e < E) {
        int d = dst[e];
        if ((unsigned)d < (unsigned)n) atomicAdd(&g_cnt[d], 1);
    }
}
__global__ void dinv_kernel(int n) {
    int i = blockIdx.x * blockDim.x + threadIdx.x;
    if (i < n) g_dinv[i] = rsqrtf(1.0f + (float)g_cnt[i]);
}
__global__ void bsum_kernel(int n) {
    __shared__ int sh[256];
    const int b = blockIdx.x, t = threadIdx.x;
    const int i = b * 256 + t;
    sh[t] = (i < n) ? g_cnt[i] : 0;
    __syncthreads();
    for (int o = 128; o; o >>= 1) {
        if (t < o) sh[t] += sh[t + o];
        __syncthreads();
    }
    if (t == 0) g_blk[b] = sh[0];
}
__global__ void bscan_kernel(int nb) {
    __shared__ int sh[256];
    const int t = threadIdx.x;
    const int v = (t < nb) ? g_blk[t] : 0;
    sh[t] = v;
    __syncthreads();
    for (int o = 1; o < 256; o <<= 1) {
        int u = (t >= o) ? sh[t - o] : 0;
        __syncthreads();
        sh[t] += u;
        __syncthreads();
    }
    if (t < nb) g_blk[t] = sh[t] - v;  // exclusive
}
__global__ void bfin_kernel(int n) {
    __shared__ int sh[256];
    const int b = blockIdx.x, t = threadIdx.x;
    const int i = b * 256 + t;
    const int v = (i < n) ? g_cnt[i] : 0;
    sh[t] = v;
    __syncthreads();
    for (int o = 1; o < 256; o <<= 1) {
        int u = (t >= o) ? sh[t - o] : 0;
        __syncthreads();
        sh[t] += u;
        __syncthreads();
    }
    if (i < n) g_start[i] = g_blk[b] + sh[t] - v;
}
__global__ void scatter_kernel(const int* __restrict__ src,
                               const int* __restrict__ dst, int E, int n) {
    int e = blockIdx.x * blockDim.x + threadIdx.x;
    if (e < E) {
        int d = dst[e], s = src[e];
        if ((unsigned)d >= (unsigned)n || (unsigned)s >= (unsigned)n) return;
        int pos = g_start[d] + atomicAdd(&g_cursor[d], 1);
        g_csrc[pos] = s;
    }
}

// ---------------------------------------------------------------------------
// xs = S @ x in 128-dim, written as split bf16. One 128-thread block per node.
// ---------------------------------------------------------------------------
__global__ __launch_bounds__(128)
void agg128_kernel(const float* __restrict__ x, int n) {
    const int node = blockIdx.x;
    const int c = threadIdx.x;
    const float di = g_dinv[node];
    float acc = di * x[(size_t)node * DIN + c];
    const int lo = g_start[node];
    const int hi = lo + g_cnt[node];
    for (int j = lo; j < hi; ++j) {
        const int s = g_csrc[j];
        acc += g_dinv[s] * x[(size_t)s * DIN + c];
    }
    const float v = di * acc;
    const bf16 h = __float2bfloat16(v);
    const size_t idx = (size_t)node * DIN + c;
    g_xs_h[idx] = h;
    g_xs_l[idx] = __float2bfloat16(v - __bfloat162float(h));
}

// ---------------------------------------------------------------------------
// Final: out[i] = h3[i,:] . W_out + b_out   (one warp per row)
// ---------------------------------------------------------------------------
__global__ void final_dot_kernel(const float* __restrict__ Wout,
                                 const float* __restrict__ bout,
                                 float* __restrict__ out, int n) {
    const int warp = (blockIdx.x * blockDim.x + threadIdx.x) >> 5;
    const int lane = threadIdx.x & 31;
    if (warp >= n) return;
    const float* row = &g_h3[(size_t)warp * HDIM];
    float s = 0.f;
#pragma unroll
    for (int i = 0; i < 8; ++i)
        s += row[lane + 32 * i] * Wout[lane + 32 * i];
#pragma unroll
    for (int o = 16; o; o >>= 1) s += __shfl_xor_sync(0xFFFFFFFFu, s, o);
    if (lane == 0) out[warp] = s + bout[0];
}

// ---------------------------------------------------------------------------
// Launch
// ---------------------------------------------------------------------------
extern "C" void kernel_launch(void* const* d_in, const int* in_sizes, int n_in,
                              void* d_out, int out_size) {
    const float* x     = (const float*)d_in[0];
    const int*   ei    = (const int*)d_in[1];
    const float* W_gcn = (const float*)d_in[2];
    const float* b_gcn = (const float*)d_in[3];
    const float* W1    = (const float*)d_in[4];
    const float* b1    = (const float*)d_in[5];
    const float* W2    = (const float*)d_in[6];
    const float* b2    = (const float*)d_in[7];
    const float* W3    = (const float*)d_in[8];
    const float* b3    = (const float*)d_in[9];
    const float* Wout  = (const float*)d_in[10];
    const float* bout  = (const float*)d_in[11];
    float* out = (float*)d_out;

    const int N = in_sizes[0] / DIN;
    const int E = in_sizes[1] / 2;
    const int* src = ei;
    const int* dst = ei + E;
    const int nb = DIV_UP(N, 256);

    bf16 *p_xs_h, *p_xs_l, *p_ag_h, *p_ag_l, *p_h1_h, *p_h1_l, *p_h2_h, *p_h2_l;
    bf16 *p_Wg_h, *p_Wg_l, *p_W1_h, *p_W1_l, *p_W2_h, *p_W2_l, *p_W3_h, *p_W3_l;
    float* p_h3;
    cudaGetSymbolAddress((void**)&p_xs_h, g_xs_h);
    cudaGetSymbolAddress((void**)&p_xs_l, g_xs_l);
    cudaGetSymbolAddress((void**)&p_ag_h, g_ag_h);
    cudaGetSymbolAddress((void**)&p_ag_l, g_ag_l);
    cudaGetSymbolAddress((void**)&p_h1_h, g_h1_h);
    cudaGetSymbolAddress((void**)&p_h1_l, g_h1_l);
    cudaGetSymbolAddress((void**)&p_h2_h, g_h2_h);
    cudaGetSymbolAddress((void**)&p_h2_l, g_h2_l);
    cudaGetSymbolAddress((void**)&p_h3, g_h3);
    cudaGetSymbolAddress((void**)&p_Wg_h, g_Wg_h);
    cudaGetSymbolAddress((void**)&p_Wg_l, g_Wg_l);
    cudaGetSymbolAddress((void**)&p_W1_h, g_W1_h);
    cudaGetSymbolAddress((void**)&p_W1_l, g_W1_l);
    cudaGetSymbolAddress((void**)&p_W2_h, g_W2_h);
    cudaGetSymbolAddress((void**)&p_W2_l, g_W2_l);
    cudaGetSymbolAddress((void**)&p_W3_h, g_W3_h);
    cudaGetSymbolAddress((void**)&p_W3_l, g_W3_l);

    const int SMEM = 65536;  // 2 stages x 32KB
    cudaFuncSetAttribute(mma_gemm<128, false, false>,
                         cudaFuncAttributeMaxDynamicSharedMemorySize, SMEM);
    cudaFuncSetAttribute(mma_gemm<512, true, false>,
                         cudaFuncAttributeMaxDynamicSharedMemorySize, SMEM);
    cudaFuncSetAttribute(mma_gemm<256, true, false>,
                         cudaFuncAttributeMaxDynamicSharedMemorySize, SMEM);
    cudaFuncSetAttribute(mma_gemm<256, true, true>,
                         cudaFuncAttributeMaxDynamicSharedMemorySize, SMEM);

    // weight prep
    prep_w<<<DIV_UP(DGCN * DIN, 256), 256>>>(W_gcn, p_Wg_h, p_Wg_l, DIN, DGCN);
    prep_w<<<DIV_UP(HDIM * DGCN, 256), 256>>>(W1, p_W1_h, p_W1_l, DGCN, HDIM);
    prep_w<<<DIV_UP(HDIM * HDIM, 256), 256>>>(W2, p_W2_h, p_W2_l, HDIM, HDIM);
    prep_w<<<DIV_UP(HDIM * HDIM, 256), 256>>>(W3, p_W3_h, p_W3_l, HDIM, HDIM);

    // CSR build + norms
    zero_kernel<<<DIV_UP(N, 256), 256>>>(N);
    hist_kernel<<<DIV_UP(E, 256), 256>>>(dst, E, N);
    dinv_kernel<<<DIV_UP(N, 256), 256>>>(N);
    bsum_kernel<<<nb, 256>>>(N);
    bscan_kernel<<<1, 256>>>(nb);
    bfin_kernel<<<nb, 256>>>(N);
    scatter_kernel<<<DIV_UP(E, 256), 256>>>(src, dst, E, N);

    // xs = S @ x  (split bf16 output)
    agg128_kernel<<<N, 128>>>(x, N);

    const int mt = DIV_UP(N, 128);
    mma_gemm<128, false, false><<<dim3(DGCN / 128, mt), 256, SMEM>>>(
        p_xs_h, p_xs_l, p_Wg_h, p_Wg_l, b_gcn, p_ag_h, p_ag_l, nullptr, DGCN);
    mma_gemm<512, true, false><<<dim3(HDIM / 128, mt), 256, SMEM>>>(
        p_ag_h, p_ag_l, p_W1_h, p_W1_l, b1, p_h1_h, p_h1_l, nullptr, HDIM);
    mma_gemm<256, true, false><<<dim3(HDIM / 128, mt), 256, SMEM>>>(
        p_h1_h, p_h1_l, p_W2_h, p_W2_l, b2, p_h2_h, p_h2_l, nullptr, HDIM);
    mma_gemm<256, true, true><<<dim3(HDIM / 128, mt), 256, SMEM>>>(
        p_h2_h, p_h2_l, p_W3_h, p_W3_l, b3, nullptr, nullptr, p_h3, HDIM);

    final_dot_kernel<<<DIV_UP(N * 32, 256), 256>>>(Wout, bout, out, N);
}

// round 9
// speedup vs baseline: 4.1224x; 1.0236x over previous
#include <cuda_runtime.h>
#include <cuda_bf16.h>
#include <stdint.h>

// ---------------------------------------------------------------------------
// N=50000, D=128, GCN out=512, H=256, E=800000. edge_index int32.
// gcn_conv(x) = (S @ x) @ W_gcn + b  (aggregate in 128-dim x-space, CSR).
// GEMMs: warp-level mma.sync bf16 3-term hi/lo split, 3-stage cp.async pipe.
// ---------------------------------------------------------------------------
#define MAXN  50000
#define MAXNP 50048      // multiple of 128; padded rows are zero
#define MAXE  800000
#define DIN   128
#define DGCN  512
#define HDIM  256
#define DIV_UP(a, b) (((a) + (b) - 1) / (b))

typedef __nv_bfloat16 bf16;

// ---- scratch (device globals; zero-initialized at module load) ----
__device__ bf16  g_xs_h[(size_t)MAXNP * DIN],  g_xs_l[(size_t)MAXNP * DIN];
__device__ bf16  g_ag_h[(size_t)MAXNP * DGCN], g_ag_l[(size_t)MAXNP * DGCN];
__device__ bf16  g_h1_h[(size_t)MAXNP * HDIM], g_h1_l[(size_t)MAXNP * HDIM];
__device__ bf16  g_h2_h[(size_t)MAXNP * HDIM], g_h2_l[(size_t)MAXNP * HDIM];
__device__ float g_h3[(size_t)MAXNP * HDIM];
// transposed + split weights  [NOUT, K]
__device__ bf16 g_Wg_h[DGCN * DIN],  g_Wg_l[DGCN * DIN];
__device__ bf16 g_W1_h[HDIM * DGCN], g_W1_l[HDIM * DGCN];
__device__ bf16 g_W2_h[HDIM * HDIM], g_W2_l[HDIM * HDIM];
__device__ bf16 g_W3_h[HDIM * HDIM], g_W3_l[HDIM * HDIM];
// graph
__device__ float g_dinv[MAXN];
__device__ int   g_cnt[MAXN], g_start[MAXN], g_cursor[MAXN], g_csrc[MAXE];
__device__ int   g_blk[256];

__device__ __forceinline__ float leaky(float v) { return v > 0.f ? v : 0.1f * v; }

__device__ __forceinline__ uint32_t smem_u32(const void* p) {
    uint32_t a;
    asm("{ .reg .u64 t; cvta.to.shared.u64 t, %1; cvt.u32.u64 %0, t; }"
        : "=r"(a) : "l"(p));
    return a;
}

// smem tile: 128 rows x 64 bytes (32 bf16); chunk = 16B; swizzle keeps
// ldmatrix 8-lane phases and cp.async writes conflict-free.
__device__ __forceinline__ uint32_t swz(int row, int chunk) {
    return (uint32_t)(row * 64 + ((chunk ^ ((row ^ (row >> 2)) & 3)) * 16));
}

// ---------------------------------------------------------------------------
// bf16x3 warp-MMA GEMM: C[M,NOUT] = split(A[M,K]) @ split(B[NOUT,K])^T
// Block 128x128, BK=32, 256 thr (8 warps, 2x4), warp tile 64x32.
// 3-stage circular cp.async pipeline, one __syncthreads per stage.
// A/C buffers padded to a multiple of 128 rows -> no bounds guards.
// ---------------------------------------------------------------------------
template <int K, bool LEAKY, bool F32OUT>
__global__ __launch_bounds__(256)
void mma_gemm(const bf16* __restrict__ Ah, const bf16* __restrict__ Al,
              const bf16* __restrict__ Bh, const bf16* __restrict__ Bl,
              const float* __restrict__ bias,
              bf16* __restrict__ Ch, bf16* __restrict__ Cl,
              float* __restrict__ Cf, int NOUT) {
    extern __shared__ char sm[];
    const uint32_t sbase = smem_u32(sm);

    const int tid = threadIdx.x;
    const int lane = tid & 31, wid = tid >> 5;
    const int wm = wid >> 2, wn = wid & 3;        // 2 x 4 warp grid
    const int brow = blockIdx.y * 128;
    const int bcol = blockIdx.x * 128;

    float acc[4][4][4] = {};
    constexpr int NST = K / 32;

    // per-thread load slots (2 chunks x 4 tiles), hoisted
    const int idx0 = tid * 2;                     // 0..510 within tile
    const int row0 = idx0 >> 2, c0 = idx0 & 3;
    const int row1 = (idx0 + 1) >> 2, c1 = (idx0 + 1) & 3;
    const uint32_t so0 = swz(row0, c0), so1 = swz(row1, c1);

    auto load_stage = [&](int s, int buf) {
        const int kofs = s * 32;
        const uint32_t sb = sbase + buf * 32768;
        const bf16* srcs[4] = {
            Ah + (size_t)brow * K + kofs, Al + (size_t)brow * K + kofs,
            Bh + (size_t)bcol * K + kofs, Bl + (size_t)bcol * K + kofs};
#pragma unroll
        for (int tile = 0; tile < 4; ++tile) {
            const bf16* base = srcs[tile];
            const uint32_t d = sb + tile * 8192;
            asm volatile("cp.async.cg.shared.global [%0], [%1], 16;"
                         :: "r"(d + so0), "l"(base + (size_t)row0 * K + c0 * 8));
            asm volatile("cp.async.cg.shared.global [%0], [%1], 16;"
                         :: "r"(d + so1), "l"(base + (size_t)row1 * K + c1 * 8));
        }
        asm volatile("cp.async.commit_group;" ::: "memory");
    };

    auto do_compute = [&](int buf) {
        const uint32_t sb = sbase + buf * 32768;
#pragma unroll
        for (int t = 0; t < 3; ++t) {             // Ah*Bh, Ah*Bl, Al*Bh
            const uint32_t Ab = sb + (t == 2 ? 8192 : 0);
            const uint32_t Bb = sb + 16384 + (t == 1 ? 8192 : 0);
#pragma unroll
            for (int ks = 0; ks < 2; ++ks) {      // two k16 steps per BK=32
                uint32_t a[4][4];
#pragma unroll
                for (int mi = 0; mi < 4; ++mi) {
                    const int row = wm * 64 + mi * 16 + (lane & 7) + ((lane >> 3) & 1) * 8;
                    const int ch = ks * 2 + (lane >> 4);
                    const uint32_t ad = Ab + swz(row, ch);
                    asm volatile(
                        "ldmatrix.sync.aligned.m8n8.x4.shared.b16 {%0,%1,%2,%3}, [%4];"
                        : "=r"(a[mi][0]), "=r"(a[mi][1]), "=r"(a[mi][2]), "=r"(a[mi][3])
                        : "r"(ad));
                }
                uint32_t b[4][2];
#pragma unroll
                for (int p = 0; p < 2; ++p) {
                    const int row = wn * 32 + p * 16 + ((lane >> 4) & 1) * 8 + (lane & 7);
                    const int ch = ks * 2 + ((lane >> 3) & 1);
                    const uint32_t bd = Bb + swz(row, ch);
                    uint32_t r0, r1, r2, r3;
                    asm volatile(
                        "ldmatrix.sync.aligned.m8n8.x4.shared.b16 {%0,%1,%2,%3}, [%4];"
                        : "=r"(r0), "=r"(r1), "=r"(r2), "=r"(r3) : "r"(bd));
                    b[p * 2][0] = r0; b[p * 2][1] = r1;
                    b[p * 2 + 1][0] = r2; b[p * 2 + 1][1] = r3;
                }
#pragma unroll
                for (int mi = 0; mi < 4; ++mi)
#pragma unroll
                    for (int ni = 0; ni < 4; ++ni)
                        asm volatile(
                            "mma.sync.aligned.m16n8k16.row.col.f32.bf16.bf16.f32 "
                            "{%0,%1,%2,%3}, {%4,%5,%6,%7}, {%8,%9}, {%0,%1,%2,%3};"
                            : "+f"(acc[mi][ni][0]), "+f"(acc[mi][ni][1]),
                              "+f"(acc[mi][ni][2]), "+f"(acc[mi][ni][3])
                            : "r"(a[mi][0]), "r"(a[mi][1]), "r"(a[mi][2]), "r"(a[mi][3]),
                              "r"(b[ni][0]), "r"(b[ni][1]));
            }
        }
    };

    // 3-stage circular pipeline, loads run 2 stages ahead
    load_stage(0, 0);
    if (NST > 1) load_stage(1, 1);
    for (int s = 0; s < NST; ++s) {
        if (s + 1 < NST)
            asm volatile("cp.async.wait_group 1;" ::: "memory");
        else
            asm volatile("cp.async.wait_group 0;" ::: "memory");
        __syncthreads();
        if (s + 2 < NST) load_stage(s + 2, (s + 2) % 3);
        do_compute(s % 3);
    }

    // ---- epilogue: bias (+leaky) (+re-split to bf16 hi/lo) ----
#pragma unroll
    for (int mi = 0; mi < 4; ++mi) {
        const int r0 = brow + wm * 64 + mi * 16 + (lane >> 2);
#pragma unroll
        for (int ni = 0; ni < 4; ++ni) {
            const int col = bcol + wn * 32 + ni * 8 + (lane & 3) * 2;
            const float2 bb = *(const float2*)&bias[col];
#pragma unroll
            for (int h = 0; h < 2; ++h) {
                const int r = r0 + h * 8;
                float v0 = acc[mi][ni][h * 2 + 0] + bb.x;
                float v1 = acc[mi][ni][h * 2 + 1] + bb.y;
                if (LEAKY) { v0 = leaky(v0); v1 = leaky(v1); }
                if (F32OUT) {
                    *(float2*)&Cf[(size_t)r * NOUT + col] = make_float2(v0, v1);
                } else {
                    const __nv_bfloat162 hv = __floats2bfloat162_rn(v0, v1);
                    *(__nv_bfloat162*)&Ch[(size_t)r * NOUT + col] = hv;
                    const float l0 = v0 - __bfloat162float(hv.x);
                    const float l1 = v1 - __bfloat162float(hv.y);
                    *(__nv_bfloat162*)&Cl[(size_t)r * NOUT + col] =
                        __floats2bfloat162_rn(l0, l1);
                }
            }
        }
    }
}

// ---------------------------------------------------------------------------
// Weight prep (all 4 weights in one kernel): transpose + split hi/lo
// ---------------------------------------------------------------------------
#define PW0 (DGCN * DIN)
#define PW1 (PW0 + HDIM * DGCN)
#define PW2 (PW1 + HDIM * HDIM)
#define PW3 (PW2 + HDIM * HDIM)
__global__ void prep_all(const float* __restrict__ Wg, const float* __restrict__ W1,
                         const float* __restrict__ W2, const float* __restrict__ W3) {
    const int g = blockIdx.x * blockDim.x + threadIdx.x;
    if (g >= PW3) return;
    const float* W; bf16 *Th, *Tl; int K, NOUT, idx;
    if (g < PW0)      { W = Wg; Th = g_Wg_h; Tl = g_Wg_l; K = DIN;  NOUT = DGCN; idx = g; }
    else if (g < PW1) { W = W1; Th = g_W1_h; Tl = g_W1_l; K = DGCN; NOUT = HDIM; idx = g - PW0; }
    else if (g < PW2) { W = W2; Th = g_W2_h; Tl = g_W2_l; K = HDIM; NOUT = HDIM; idx = g - PW1; }
    else              { W = W3; Th = g_W3_h; Tl = g_W3_l; K = HDIM; NOUT = HDIM; idx = g - PW2; }
    const int n = idx / K, k = idx % K;
    const float v = W[(size_t)k * NOUT + n];
    const bf16 h = __float2bfloat16(v);
    Th[idx] = h;
    Tl[idx] = __float2bfloat16(v - __bfloat162float(h));
}

// ---------------------------------------------------------------------------
// CSR build
// ---------------------------------------------------------------------------
__global__ void zero_kernel(int n) {
    int i = blockIdx.x * blockDim.x + threadIdx.x;
    if (i < n) { g_cnt[i] = 0; g_cursor[i] = 0; }
}
__global__ void hist_kernel(const int* __restrict__ dst, int E, int n) {
    int e = blockIdx.x * blockDim.x + threadIdx.x;
    if (e < E) {
        int d = dst[e];
        if ((unsigned)d < (unsigned)n) atomicAdd(&g_cnt[d], 1);
    }
}
__global__ void dinv_kernel(int n) {
    int i = blockIdx.x * blockDim.x + threadIdx.x;
    if (i < n) g_dinv[i] = rsqrtf(1.0f + (float)g_cnt[i]);
}
__global__ void bsum_kernel(int n) {
    __shared__ int sh[256];
    const int b = blockIdx.x, t = threadIdx.x;
    const int i = b * 256 + t;
    sh[t] = (i < n) ? g_cnt[i] : 0;
    __syncthreads();
    for (int o = 128; o; o >>= 1) {
        if (t < o) sh[t] += sh[t + o];
        __syncthreads();
    }
    if (t == 0) g_blk[b] = sh[0];
}
__global__ void bscan_kernel(int nb) {
    __shared__ int sh[256];
    const int t = threadIdx.x;
    const int v = (t < nb) ? g_blk[t] : 0;
    sh[t] = v;
    __syncthreads();
    for (int o = 1; o < 256; o <<= 1) {
        int u = (t >= o) ? sh[t - o] : 0;
        __syncthreads();
        sh[t] += u;
        __syncthreads();
    }
    if (t < nb) g_blk[t] = sh[t] - v;  // exclusive
}
__global__ void bfin_kernel(int n) {
    __shared__ int sh[256];
    const int b = blockIdx.x, t = threadIdx.x;
    const int i = b * 256 + t;
    const int v = (i < n) ? g_cnt[i] : 0;
    sh[t] = v;
    __syncthreads();
    for (int o = 1; o < 256; o <<= 1) {
        int u = (t >= o) ? sh[t - o] : 0;
        __syncthreads();
        sh[t] += u;
        __syncthreads();
    }
    if (i < n) g_start[i] = g_blk[b] + sh[t] - v;
}
__global__ void scatter_kernel(const int* __restrict__ src,
                               const int* __restrict__ dst, int E, int n) {
    int e = blockIdx.x * blockDim.x + threadIdx.x;
    if (e < E) {
        int d = dst[e], s = src[e];
        if ((unsigned)d >= (unsigned)n || (unsigned)s >= (unsigned)n) return;
        int pos = g_start[d] + atomicAdd(&g_cursor[d], 1);
        g_csrc[pos] = s;
    }
}

// ---------------------------------------------------------------------------
// xs = S @ x: warp per node, lane = 4 cols (float4). Split bf16 output.
// ---------------------------------------------------------------------------
__global__ __launch_bounds__(256)
void agg_warp_kernel(const float* __restrict__ x, int n) {
    const int node = (blockIdx.x * blockDim.x + threadIdx.x) >> 5;
    if (node >= n) return;
    const int lane = threadIdx.x & 31;
    const float di = g_dinv[node];
    float4 v = *(const float4*)&x[(size_t)node * DIN + lane * 4];
    float a0 = di * v.x, a1 = di * v.y, a2 = di * v.z, a3 = di * v.w;
    const int lo = g_start[node];
    const int hi = lo + g_cnt[node];
    for (int j = lo; j < hi; ++j) {
        const int s = g_csrc[j];
        const float ds = g_dinv[s];
        const float4 u = *(const float4*)&x[(size_t)s * DIN + lane * 4];
        a0 += ds * u.x; a1 += ds * u.y; a2 += ds * u.z; a3 += ds * u.w;
    }
    a0 *= di; a1 *= di; a2 *= di; a3 *= di;
    const size_t idx = (size_t)node * DIN + lane * 4;
    const __nv_bfloat162 h01 = __floats2bfloat162_rn(a0, a1);
    const __nv_bfloat162 h23 = __floats2bfloat162_rn(a2, a3);
    *(__nv_bfloat162*)&g_xs_h[idx] = h01;
    *(__nv_bfloat162*)&g_xs_h[idx + 2] = h23;
    *(__nv_bfloat162*)&g_xs_l[idx] = __floats2bfloat162_rn(
        a0 - __bfloat162float(h01.x), a1 - __bfloat162float(h01.y));
    *(__nv_bfloat162*)&g_xs_l[idx + 2] = __floats2bfloat162_rn(
        a2 - __bfloat162float(h23.x), a3 - __bfloat162float(h23.y));
}

// ---------------------------------------------------------------------------
// Final: out[i] = h3[i,:] . W_out + b_out   (one warp per row)
// ---------------------------------------------------------------------------
__global__ void final_dot_kernel(const float* __restrict__ Wout,
                                 const float* __restrict__ bout,
                                 float* __restrict__ out, int n) {
    const int warp = (blockIdx.x * blockDim.x + threadIdx.x) >> 5;
    const int lane = threadIdx.x & 31;
    if (warp >= n) return;
    const float* row = &g_h3[(size_t)warp * HDIM];
    float s = 0.f;
#pragma unroll
    for (int i = 0; i < 8; ++i)
        s += row[lane + 32 * i] * Wout[lane + 32 * i];
#pragma unroll
    for (int o = 16; o; o >>= 1) s += __shfl_xor_sync(0xFFFFFFFFu, s, o);
    if (lane == 0) out[warp] = s + bout[0];
}

// ---------------------------------------------------------------------------
// Launch
// ---------------------------------------------------------------------------
extern "C" void kernel_launch(void* const* d_in, const int* in_sizes, int n_in,
                              void* d_out, int out_size) {
    const float* x     = (const float*)d_in[0];
    const int*   ei    = (const int*)d_in[1];
    const float* W_gcn = (const float*)d_in[2];
    const float* b_gcn = (const float*)d_in[3];
    const float* W1    = (const float*)d_in[4];
    const float* b1    = (const float*)d_in[5];
    const float* W2    = (const float*)d_in[6];
    const float* b2    = (const float*)d_in[7];
    const float* W3    = (const float*)d_in[8];
    const float* b3    = (const float*)d_in[9];
    const float* Wout  = (const float*)d_in[10];
    const float* bout  = (const float*)d_in[11];
    float* out = (float*)d_out;

    const int N = in_sizes[0] / DIN;
    const int E = in_sizes[1] / 2;
    const int* src = ei;
    const int* dst = ei + E;
    const int nb = DIV_UP(N, 256);

    bf16 *p_xs_h, *p_xs_l, *p_ag_h, *p_ag_l, *p_h1_h, *p_h1_l, *p_h2_h, *p_h2_l;
    bf16 *p_Wg_h, *p_Wg_l, *p_W1_h, *p_W1_l, *p_W2_h, *p_W2_l, *p_W3_h, *p_W3_l;
    float* p_h3;
    cudaGetSymbolAddress((void**)&p_xs_h, g_xs_h);
    cudaGetSymbolAddress((void**)&p_xs_l, g_xs_l);
    cudaGetSymbolAddress((void**)&p_ag_h, g_ag_h);
    cudaGetSymbolAddress((void**)&p_ag_l, g_ag_l);
    cudaGetSymbolAddress((void**)&p_h1_h, g_h1_h);
    cudaGetSymbolAddress((void**)&p_h1_l, g_h1_l);
    cudaGetSymbolAddress((void**)&p_h2_h, g_h2_h);
    cudaGetSymbolAddress((void**)&p_h2_l, g_h2_l);
    cudaGetSymbolAddress((void**)&p_h3, g_h3);
    cudaGetSymbolAddress((void**)&p_Wg_h, g_Wg_h);
    cudaGetSymbolAddress((void**)&p_Wg_l, g_Wg_l);
    cudaGetSymbolAddress((void**)&p_W1_h, g_W1_h);
    cudaGetSymbolAddress((void**)&p_W1_l, g_W1_l);
    cudaGetSymbolAddress((void**)&p_W2_h, g_W2_h);
    cudaGetSymbolAddress((void**)&p_W2_l, g_W2_l);
    cudaGetSymbolAddress((void**)&p_W3_h, g_W3_h);
    cudaGetSymbolAddress((void**)&p_W3_l, g_W3_l);

    const int SMEM = 98304;  // 3 stages x 32KB
    cudaFuncSetAttribute(mma_gemm<128, false, false>,
                         cudaFuncAttributeMaxDynamicSharedMemorySize, SMEM);
    cudaFuncSetAttribute(mma_gemm<512, true, false>,
                         cudaFuncAttributeMaxDynamicSharedMemorySize, SMEM);
    cudaFuncSetAttribute(mma_gemm<256, true, false>,
                         cudaFuncAttributeMaxDynamicSharedMemorySize, SMEM);
    cudaFuncSetAttribute(mma_gemm<256, true, true>,
                         cudaFuncAttributeMaxDynamicSharedMemorySize, SMEM);

    // weight prep (single kernel)
    prep_all<<<DIV_UP(PW3, 256), 256>>>(W_gcn, W1, W2, W3);

    // CSR build + norms
    zero_kernel<<<DIV_UP(N, 256), 256>>>(N);
    hist_kernel<<<DIV_UP(E, 256), 256>>>(dst, E, N);
    dinv_kernel<<<DIV_UP(N, 256), 256>>>(N);
    bsum_kernel<<<nb, 256>>>(N);
    bscan_kernel<<<1, 256>>>(nb);
    bfin_kernel<<<nb, 256>>>(N);
    scatter_kernel<<<DIV_UP(E, 256), 256>>>(src, dst, E, N);

    // xs = S @ x  (split bf16 output), warp per node
    agg_warp_kernel<<<DIV_UP(N * 32, 256), 256>>>(x, N);

    const int mt = DIV_UP(N, 128);
    mma_gemm<128, false, false><<<dim3(DGCN / 128, mt), 256, SMEM>>>(
        p_xs_h, p_xs_l, p_Wg_h, p_Wg_l, b_gcn, p_ag_h, p_ag_l, nullptr, DGCN);
    mma_gemm<512, true, false><<<dim3(HDIM / 128, mt), 256, SMEM>>>(
        p_ag_h, p_ag_l, p_W1_h, p_W1_l, b1, p_h1_h, p_h1_l, nullptr, HDIM);
    mma_gemm<256, true, false><<<dim3(HDIM / 128, mt), 256, SMEM>>>(
        p_h1_h, p_h1_l, p_W2_h, p_W2_l, b2, p_h2_h, p_h2_l, nullptr, HDIM);
    mma_gemm<256, true, true><<<dim3(HDIM / 128, mt), 256, SMEM>>>(
        p_h2_h, p_h2_l, p_W3_h, p_W3_l, b3, nullptr, nullptr, p_h3, HDIM);

    final_dot_kernel<<<DIV_UP(N * 32, 256), 256>>>(Wout, bout, out, N);
}

// round 10
// speedup vs baseline: 4.8933x; 1.1870x over previous
#include <cuda_runtime.h>
#include <cuda_bf16.h>
#include <stdint.h>

// ---------------------------------------------------------------------------
// N=50000, D=128, GCN out=512, H=256, E=800000. edge_index int32.
// gcn_conv(x) = (S @ x) @ W_gcn + b  (aggregate in 128-dim x-space, CSR).
// GEMMs: mma.sync bf16 3-term hi/lo split; fragment reuse across terms;
// 3-stage cp.async pipeline; __launch_bounds__(256,2) for 2 CTAs/SM.
// ---------------------------------------------------------------------------
#define MAXN  50000
#define MAXNP 50048      // multiple of 128; padded rows are zero
#define MAXE  800000
#define DIN   128
#define DGCN  512
#define HDIM  256
#define DIV_UP(a, b) (((a) + (b) - 1) / (b))

typedef __nv_bfloat16 bf16;

// ---- scratch (device globals; zero-initialized at module load) ----
__device__ bf16  g_xs_h[(size_t)MAXNP * DIN],  g_xs_l[(size_t)MAXNP * DIN];
__device__ bf16  g_ag_h[(size_t)MAXNP * DGCN], g_ag_l[(size_t)MAXNP * DGCN];
__device__ bf16  g_h1_h[(size_t)MAXNP * HDIM], g_h1_l[(size_t)MAXNP * HDIM];
__device__ bf16  g_h2_h[(size_t)MAXNP * HDIM], g_h2_l[(size_t)MAXNP * HDIM];
__device__ float g_h3[(size_t)MAXNP * HDIM];
// transposed + split weights  [NOUT, K]
__device__ bf16 g_Wg_h[DGCN * DIN],  g_Wg_l[DGCN * DIN];
__device__ bf16 g_W1_h[HDIM * DGCN], g_W1_l[HDIM * DGCN];
__device__ bf16 g_W2_h[HDIM * HDIM], g_W2_l[HDIM * HDIM];
__device__ bf16 g_W3_h[HDIM * HDIM], g_W3_l[HDIM * HDIM];
// graph
__device__ float g_dinv[MAXN];
__device__ int   g_cnt[MAXN], g_start[MAXN], g_csrc[MAXE];
__device__ int   g_blk[256];

__device__ __forceinline__ float leaky(float v) { return v > 0.f ? v : 0.1f * v; }

__device__ __forceinline__ uint32_t smem_u32(const void* p) {
    uint32_t a;
    asm("{ .reg .u64 t; cvta.to.shared.u64 t, %1; cvt.u32.u64 %0, t; }"
        : "=r"(a) : "l"(p));
    return a;
}

// smem tile: 128 rows x 64 bytes (32 bf16); chunk = 16B; swizzle keeps
// ldmatrix 8-lane phases and cp.async writes conflict-free.
__device__ __forceinline__ uint32_t swz(int row, int chunk) {
    return (uint32_t)(row * 64 + ((chunk ^ ((row ^ (row >> 2)) & 3)) * 16));
}

#define LDSM4(r, addr)                                                         \
    asm volatile("ldmatrix.sync.aligned.m8n8.x4.shared.b16 {%0,%1,%2,%3}, [%4];" \
                 : "=r"((r)[0]), "=r"((r)[1]), "=r"((r)[2]), "=r"((r)[3])      \
                 : "r"(addr))

#define MMA16(c, av, b0, b1)                                                   \
    asm volatile("mma.sync.aligned.m16n8k16.row.col.f32.bf16.bf16.f32 "        \
                 "{%0,%1,%2,%3}, {%4,%5,%6,%7}, {%8,%9}, {%0,%1,%2,%3};"       \
                 : "+f"((c)[0]), "+f"((c)[1]), "+f"((c)[2]), "+f"((c)[3])      \
                 : "r"((av)[0]), "r"((av)[1]), "r"((av)[2]), "r"((av)[3]),     \
                   "r"(b0), "r"(b1))

// ---------------------------------------------------------------------------
// bf16x3 warp-MMA GEMM: C[M,NOUT] = split(A[M,K]) @ split(B[NOUT,K])^T
// Block 128x128, BK=32, 256 thr (8 warps, 2x4), warp tile 64x32.
// Fragment reuse: per k16-step load Ah,Bh (t0), Bl (t1, reuse Ah),
// Al into Ah's regs (t2, reuse Bh). 12 LDSM + 48 MMA per ks-pair... per ks.
// ---------------------------------------------------------------------------
template <int K, bool LEAKY, bool F32OUT>
__global__ __launch_bounds__(256, 2)
void mma_gemm(const bf16* __restrict__ Ah, const bf16* __restrict__ Al,
              const bf16* __restrict__ Bh, const bf16* __restrict__ Bl,
              const float* __restrict__ bias,
              bf16* __restrict__ Ch, bf16* __restrict__ Cl,
              float* __restrict__ Cf, int NOUT) {
    extern __shared__ char sm[];
    const uint32_t sbase = smem_u32(sm);

    const int tid = threadIdx.x;
    const int lane = tid & 31, wid = tid >> 5;
    const int wm = wid >> 2, wn = wid & 3;        // 2 x 4 warp grid
    const int brow = blockIdx.y * 128;
    const int bcol = blockIdx.x * 128;

    float acc[4][4][4] = {};
    constexpr int NST = K / 32;

    // per-thread cp.async slots (2 chunks x 4 tiles), hoisted
    const int idx0 = tid * 2;                     // 0..510 within tile
    const int row0 = idx0 >> 2, c0 = idx0 & 3;
    const int row1 = (idx0 + 1) >> 2, c1 = (idx0 + 1) & 3;
    const uint32_t so0 = swz(row0, c0), so1 = swz(row1, c1);

    auto load_stage = [&](int s, int buf) {
        const int kofs = s * 32;
        const uint32_t sb = sbase + buf * 32768;
        const bf16* srcs[4] = {
            Ah + (size_t)brow * K + kofs, Al + (size_t)brow * K + kofs,
            Bh + (size_t)bcol * K + kofs, Bl + (size_t)bcol * K + kofs};
#pragma unroll
        for (int tile = 0; tile < 4; ++tile) {
            const bf16* base = srcs[tile];
            const uint32_t d = sb + tile * 8192;
            asm volatile("cp.async.cg.shared.global [%0], [%1], 16;"
                         :: "r"(d + so0), "l"(base + (size_t)row0 * K + c0 * 8));
            asm volatile("cp.async.cg.shared.global [%0], [%1], 16;"
                         :: "r"(d + so1), "l"(base + (size_t)row1 * K + c1 * 8));
        }
        asm volatile("cp.async.commit_group;" ::: "memory");
    };

    // ldmatrix address pieces (constant per thread across stages)
    const int arow_base = wm * 64 + (lane & 7) + ((lane >> 3) & 1) * 8;
    const int ach_half = lane >> 4;                       // 0/1
    const int brow_base = wn * 32 + ((lane >> 4) & 1) * 8 + (lane & 7);
    const int bch_half = (lane >> 3) & 1;                 // 0/1

    auto do_compute = [&](int buf) {
        const uint32_t sb = sbase + buf * 32768;
        const uint32_t Ahb = sb, Alb = sb + 8192;
        const uint32_t Bhb = sb + 16384, Blb = sb + 24576;
#pragma unroll
        for (int ks = 0; ks < 2; ++ks) {
            const int ach = ks * 2 + ach_half;
            const int bch = ks * 2 + bch_half;
            uint32_t a[4][4], bh[4][2], bl[4][2];
            // Ah fragments
#pragma unroll
            for (int mi = 0; mi < 4; ++mi)
                LDSM4(a[mi], Ahb + swz(arow_base + mi * 16, ach));
            // Bh fragments
#pragma unroll
            for (int p = 0; p < 2; ++p) {
                uint32_t r[4];
                LDSM4(r, Bhb + swz(brow_base + p * 16, bch));
                bh[p * 2][0] = r[0]; bh[p * 2][1] = r[1];
                bh[p * 2 + 1][0] = r[2]; bh[p * 2 + 1][1] = r[3];
            }
            // t0: Ah x Bh
#pragma unroll
            for (int mi = 0; mi < 4; ++mi)
#pragma unroll
                for (int ni = 0; ni < 4; ++ni)
                    MMA16(acc[mi][ni], a[mi], bh[ni][0], bh[ni][1]);
            // Bl fragments
#pragma unroll
            for (int p = 0; p < 2; ++p) {
                uint32_t r[4];
                LDSM4(r, Blb + swz(brow_base + p * 16, bch));
                bl[p * 2][0] = r[0]; bl[p * 2][1] = r[1];
                bl[p * 2 + 1][0] = r[2]; bl[p * 2 + 1][1] = r[3];
            }
            // t1: Ah x Bl  (reuse a)
#pragma unroll
            for (int mi = 0; mi < 4; ++mi)
#pragma unroll
                for (int ni = 0; ni < 4; ++ni)
                    MMA16(acc[mi][ni], a[mi], bl[ni][0], bl[ni][1]);
            // Al fragments (overwrite a)
#pragma unroll
            for (int mi = 0; mi < 4; ++mi)
                LDSM4(a[mi], Alb + swz(arow_base + mi * 16, ach));
            // t2: Al x Bh  (reuse bh)
#pragma unroll
            for (int mi = 0; mi < 4; ++mi)
#pragma unroll
                for (int ni = 0; ni < 4; ++ni)
                    MMA16(acc[mi][ni], a[mi], bh[ni][0], bh[ni][1]);
        }
    };

    // 3-stage circular pipeline, loads run 2 stages ahead
    load_stage(0, 0);
    if (NST > 1) load_stage(1, 1);
    for (int s = 0; s < NST; ++s) {
        if (s + 1 < NST)
            asm volatile("cp.async.wait_group 1;" ::: "memory");
        else
            asm volatile("cp.async.wait_group 0;" ::: "memory");
        __syncthreads();
        if (s + 2 < NST) load_stage(s + 2, (s + 2) % 3);
        do_compute(s % 3);
    }

    // ---- epilogue: bias (+leaky) (+re-split to bf16 hi/lo) ----
#pragma unroll
    for (int mi = 0; mi < 4; ++mi) {
        const int r0 = brow + wm * 64 + mi * 16 + (lane >> 2);
#pragma unroll
        for (int ni = 0; ni < 4; ++ni) {
            const int col = bcol + wn * 32 + ni * 8 + (lane & 3) * 2;
            const float2 bb = *(const float2*)&bias[col];
#pragma unroll
            for (int h = 0; h < 2; ++h) {
                const int r = r0 + h * 8;
                float v0 = acc[mi][ni][h * 2 + 0] + bb.x;
                float v1 = acc[mi][ni][h * 2 + 1] + bb.y;
                if (LEAKY) { v0 = leaky(v0); v1 = leaky(v1); }
                if (F32OUT) {
                    *(float2*)&Cf[(size_t)r * NOUT + col] = make_float2(v0, v1);
                } else {
                    const __nv_bfloat162 hv = __floats2bfloat162_rn(v0, v1);
                    *(__nv_bfloat162*)&Ch[(size_t)r * NOUT + col] = hv;
                    const float l0 = v0 - __bfloat162float(hv.x);
                    const float l1 = v1 - __bfloat162float(hv.y);
                    *(__nv_bfloat162*)&Cl[(size_t)r * NOUT + col] =
                        __floats2bfloat162_rn(l0, l1);
                }
            }
        }
    }
}

// ---------------------------------------------------------------------------
// Weight prep (all 4 weights in one kernel): transpose + split hi/lo
// ---------------------------------------------------------------------------
#define PW0 (DGCN * DIN)
#define PW1 (PW0 + HDIM * DGCN)
#define PW2 (PW1 + HDIM * HDIM)
#define PW3 (PW2 + HDIM * HDIM)
__global__ void prep_all(const float* __restrict__ Wg, const float* __restrict__ W1,
                         const float* __restrict__ W2, const float* __restrict__ W3) {
    const int g = blockIdx.x * blockDim.x + threadIdx.x;
    if (g >= PW3) return;
    const float* W; bf16 *Th, *Tl; int K, NOUT, idx;
    if (g < PW0)      { W = Wg; Th = g_Wg_h; Tl = g_Wg_l; K = DIN;  NOUT = DGCN; idx = g; }
    else if (g < PW1) { W = W1; Th = g_W1_h; Tl = g_W1_l; K = DGCN; NOUT = HDIM; idx = g - PW0; }
    else if (g < PW2) { W = W2; Th = g_W2_h; Tl = g_W2_l; K = HDIM; NOUT = HDIM; idx = g - PW1; }
    else              { W = W3; Th = g_W3_h; Tl = g_W3_l; K = HDIM; NOUT = HDIM; idx = g - PW2; }
    const int n = idx / K, k = idx % K;
    const float v = W[(size_t)k * NOUT + n];
    const bf16 h = __float2bfloat16(v);
    Th[idx] = h;
    Tl[idx] = __float2bfloat16(v - __bfloat162float(h));
}

// ---------------------------------------------------------------------------
// CSR build (no cursor array; scatter bumps g_start, agg derives lo=start-cnt)
// ---------------------------------------------------------------------------
__global__ void zero_kernel(int n) {
    int i = blockIdx.x * blockDim.x + threadIdx.x;
    if (i < n) g_cnt[i] = 0;
}
__global__ void hist_kernel(const int* __restrict__ dst, int E, int n) {
    int e = blockIdx.x * blockDim.x + threadIdx.x;
    if (e < E) {
        int d = dst[e];
        if ((unsigned)d < (unsigned)n) atomicAdd(&g_cnt[d], 1);
    }
}
__global__ void bsum_kernel(int n) {
    __shared__ int sh[256];
    const int b = blockIdx.x, t = threadIdx.x;
    const int i = b * 256 + t;
    sh[t] = (i < n) ? g_cnt[i] : 0;
    __syncthreads();
    for (int o = 128; o; o >>= 1) {
        if (t < o) sh[t] += sh[t + o];
        __syncthreads();
    }
    if (t == 0) g_blk[b] = sh[0];
}
__global__ void bscan_kernel(int nb) {
    __shared__ int sh[256];
    const int t = threadIdx.x;
    const int v = (t < nb) ? g_blk[t] : 0;
    sh[t] = v;
    __syncthreads();
    for (int o = 1; o < 256; o <<= 1) {
        int u = (t >= o) ? sh[t - o] : 0;
        __syncthreads();
        sh[t] += u;
        __syncthreads();
    }
    if (t < nb) g_blk[t] = sh[t] - v;  // exclusive
}
// exclusive scan finalize + dinv (fused)
__global__ void bfin_kernel(int n) {
    __shared__ int sh[256];
    const int b = blockIdx.x, t = threadIdx.x;
    const int i = b * 256 + t;
    const int v = (i < n) ? g_cnt[i] : 0;
    sh[t] = v;
    __syncthreads();
    for (int o = 1; o < 256; o <<= 1) {
        int u = (t >= o) ? sh[t - o] : 0;
        __syncthreads();
        sh[t] += u;
        __syncthreads();
    }
    if (i < n) {
        g_start[i] = g_blk[b] + sh[t] - v;
        g_dinv[i] = rsqrtf(1.0f + (float)v);
    }
}
__global__ void scatter_kernel(const int* __restrict__ src,
                               const int* __restrict__ dst, int E, int n) {
    int e = blockIdx.x * blockDim.x + threadIdx.x;
    if (e < E) {
        int d = dst[e], s = src[e];
        if ((unsigned)d >= (unsigned)n || (unsigned)s >= (unsigned)n) return;
        int pos = atomicAdd(&g_start[d], 1);
        g_csrc[pos] = s;
    }
}

// ---------------------------------------------------------------------------
// xs = S @ x: warp per node, lane = 4 cols (float4). Split bf16 output.
// After scatter, g_start[node] = segment END; lo = end - cnt.
// ---------------------------------------------------------------------------
__global__ __launch_bounds__(256)
void agg_warp_kernel(const float* __restrict__ x, int n) {
    const int node = (blockIdx.x * blockDim.x + threadIdx.x) >> 5;
    if (node >= n) return;
    const int lane = threadIdx.x & 31;
    const float di = g_dinv[node];
    float4 v = *(const float4*)&x[(size_t)node * DIN + lane * 4];
    float a0 = di * v.x, a1 = di * v.y, a2 = di * v.z, a3 = di * v.w;
    const int hi = g_start[node];
    const int lo = hi - g_cnt[node];
    for (int j = lo; j < hi; ++j) {
        const int s = g_csrc[j];
        const float ds = g_dinv[s];
        const float4 u = *(const float4*)&x[(size_t)s * DIN + lane * 4];
        a0 += ds * u.x; a1 += ds * u.y; a2 += ds * u.z; a3 += ds * u.w;
    }
    a0 *= di; a1 *= di; a2 *= di; a3 *= di;
    const size_t idx = (size_t)node * DIN + lane * 4;
    const __nv_bfloat162 h01 = __floats2bfloat162_rn(a0, a1);
    const __nv_bfloat162 h23 = __floats2bfloat162_rn(a2, a3);
    *(__nv_bfloat162*)&g_xs_h[idx] = h01;
    *(__nv_bfloat162*)&g_xs_h[idx + 2] = h23;
    *(__nv_bfloat162*)&g_xs_l[idx] = __floats2bfloat162_rn(
        a0 - __bfloat162float(h01.x), a1 - __bfloat162float(h01.y));
    *(__nv_bfloat162*)&g_xs_l[idx + 2] = __floats2bfloat162_rn(
        a2 - __bfloat162float(h23.x), a3 - __bfloat162float(h23.y));
}

// ---------------------------------------------------------------------------
// Final: out[i] = h3[i,:] . W_out + b_out   (one warp per row)
// ---------------------------------------------------------------------------
__global__ void final_dot_kernel(const float* __restrict__ Wout,
                                 const float* __restrict__ bout,
                                 float* __restrict__ out, int n) {
    const int warp = (blockIdx.x * blockDim.x + threadIdx.x) >> 5;
    const int lane = threadIdx.x & 31;
    if (warp >= n) return;
    const float* row = &g_h3[(size_t)warp * HDIM];
    float s = 0.f;
#pragma unroll
    for (int i = 0; i < 8; ++i)
        s += row[lane + 32 * i] * Wout[lane + 32 * i];
#pragma unroll
    for (int o = 16; o; o >>= 1) s += __shfl_xor_sync(0xFFFFFFFFu, s, o);
    if (lane == 0) out[warp] = s + bout[0];
}

// ---------------------------------------------------------------------------
// Launch
// ---------------------------------------------------------------------------
extern "C" void kernel_launch(void* const* d_in, const int* in_sizes, int n_in,
                              void* d_out, int out_size) {
    const float* x     = (const float*)d_in[0];
    const int*   ei    = (const int*)d_in[1];
    const float* W_gcn = (const float*)d_in[2];
    const float* b_gcn = (const float*)d_in[3];
    const float* W1    = (const float*)d_in[4];
    const float* b1    = (const float*)d_in[5];
    const float* W2    = (const float*)d_in[6];
    const float* b2    = (const float*)d_in[7];
    const float* W3    = (const float*)d_in[8];
    const float* b3    = (const float*)d_in[9];
    const float* Wout  = (const float*)d_in[10];
    const float* bout  = (const float*)d_in[11];
    float* out = (float*)d_out;

    const int N = in_sizes[0] / DIN;
    const int E = in_sizes[1] / 2;
    const int* src = ei;
    const int* dst = ei + E;
    const int nb = DIV_UP(N, 256);

    bf16 *p_xs_h, *p_xs_l, *p_ag_h, *p_ag_l, *p_h1_h, *p_h1_l, *p_h2_h, *p_h2_l;
    bf16 *p_Wg_h, *p_Wg_l, *p_W1_h, *p_W1_l, *p_W2_h, *p_W2_l, *p_W3_h, *p_W3_l;
    float* p_h3;
    cudaGetSymbolAddress((void**)&p_xs_h, g_xs_h);
    cudaGetSymbolAddress((void**)&p_xs_l, g_xs_l);
    cudaGetSymbolAddress((void**)&p_ag_h, g_ag_h);
    cudaGetSymbolAddress((void**)&p_ag_l, g_ag_l);
    cudaGetSymbolAddress((void**)&p_h1_h, g_h1_h);
    cudaGetSymbolAddress((void**)&p_h1_l, g_h1_l);
    cudaGetSymbolAddress((void**)&p_h2_h, g_h2_h);
    cudaGetSymbolAddress((void**)&p_h2_l, g_h2_l);
    cudaGetSymbolAddress((void**)&p_h3, g_h3);
    cudaGetSymbolAddress((void**)&p_Wg_h, g_Wg_h);
    cudaGetSymbolAddress((void**)&p_Wg_l, g_Wg_l);
    cudaGetSymbolAddress((void**)&p_W1_h, g_W1_h);
    cudaGetSymbolAddress((void**)&p_W1_l, g_W1_l);
    cudaGetSymbolAddress((void**)&p_W2_h, g_W2_h);
    cudaGetSymbolAddress((void**)&p_W2_l, g_W2_l);
    cudaGetSymbolAddress((void**)&p_W3_h, g_W3_h);
    cudaGetSymbolAddress((void**)&p_W3_l, g_W3_l);

    const int SMEM = 98304;  // 3 stages x 32KB
    cudaFuncSetAttribute(mma_gemm<128, false, false>,
                         cudaFuncAttributeMaxDynamicSharedMemorySize, SMEM);
    cudaFuncSetAttribute(mma_gemm<512, true, false>,
                         cudaFuncAttributeMaxDynamicSharedMemorySize, SMEM);
    cudaFuncSetAttribute(mma_gemm<256, true, false>,
                         cudaFuncAttributeMaxDynamicSharedMemorySize, SMEM);
    cudaFuncSetAttribute(mma_gemm<256, true, true>,
                         cudaFuncAttributeMaxDynamicSharedMemorySize, SMEM);

    // weight prep (single kernel)
    prep_all<<<DIV_UP(PW3, 256), 256>>>(W_gcn, W1, W2, W3);

    // CSR build + norms
    zero_kernel<<<DIV_UP(N, 256), 256>>>(N);
    hist_kernel<<<DIV_UP(E, 256), 256>>>(dst, E, N);
    bsum_kernel<<<nb, 256>>>(N);
    bscan_kernel<<<1, 256>>>(nb);
    bfin_kernel<<<nb, 256>>>(N);   // also computes g_dinv
    scatter_kernel<<<DIV_UP(E, 256), 256>>>(src, dst, E, N);

    // xs = S @ x  (split bf16 output), warp per node
    agg_warp_kernel<<<DIV_UP(N * 32, 256), 256>>>(x, N);

    const int mt = DIV_UP(N, 128);
    mma_gemm<128, false, false><<<dim3(DGCN / 128, mt), 256, SMEM>>>(
        p_xs_h, p_xs_l, p_Wg_h, p_Wg_l, b_gcn, p_ag_h, p_ag_l, nullptr, DGCN);
    mma_gemm<512, true, false><<<dim3(HDIM / 128, mt), 256, SMEM>>>(
        p_ag_h, p_ag_l, p_W1_h, p_W1_l, b1, p_h1_h, p_h1_l, nullptr, HDIM);
    mma_gemm<256, true, false><<<dim3(HDIM / 128, mt), 256, SMEM>>>(
        p_h1_h, p_h1_l, p_W2_h, p_W2_l, b2, p_h2_h, p_h2_l, nullptr, HDIM);
    mma_gemm<256, true, true><<<dim3(HDIM / 128, mt), 256, SMEM>>>(
        p_h2_h, p_h2_l, p_W3_h, p_W3_l, b3, nullptr, nullptr, p_h3, HDIM);

    final_dot_kernel<<<DIV_UP(N * 32, 256), 256>>>(Wout, bout, out, N);
}

// round 11
// speedup vs baseline: 5.0334x; 1.0286x over previous
#include <cuda_runtime.h>
#include <cuda_bf16.h>
#include <stdint.h>

// ---------------------------------------------------------------------------
// N=50000, D=128, GCN out=512, H=256, E=800000. edge_index int32.
// gcn_conv(x) = (S @ x) @ W_gcn + b  (aggregate in 128-dim x-space, CSR).
// GEMMs: mma.sync bf16 3-term hi/lo split; fragment reuse; 3-stage cp.async;
// final W_out dot fused into GEMM4 epilogue (atomicAdd partial row dots).
// ---------------------------------------------------------------------------
#define MAXN  50000
#define MAXNP 50048      // multiple of 128; padded rows are zero
#define MAXE  800000
#define DIN   128
#define DGCN  512
#define HDIM  256
#define DIV_UP(a, b) (((a) + (b) - 1) / (b))

typedef __nv_bfloat16 bf16;

// ---- scratch (device globals; zero-initialized at module load) ----
__device__ bf16  g_xs_h[(size_t)MAXNP * DIN],  g_xs_l[(size_t)MAXNP * DIN];
__device__ bf16  g_ag_h[(size_t)MAXNP * DGCN], g_ag_l[(size_t)MAXNP * DGCN];
__device__ bf16  g_h1_h[(size_t)MAXNP * HDIM], g_h1_l[(size_t)MAXNP * HDIM];
__device__ bf16  g_h2_h[(size_t)MAXNP * HDIM], g_h2_l[(size_t)MAXNP * HDIM];
// transposed + split weights  [NOUT, K]
__device__ bf16 g_Wg_h[DGCN * DIN],  g_Wg_l[DGCN * DIN];
__device__ bf16 g_W1_h[HDIM * DGCN], g_W1_l[HDIM * DGCN];
__device__ bf16 g_W2_h[HDIM * HDIM], g_W2_l[HDIM * HDIM];
__device__ bf16 g_W3_h[HDIM * HDIM], g_W3_l[HDIM * HDIM];
// graph
__device__ float g_dinv[MAXN];
__device__ int   g_cnt[MAXN], g_start[MAXN], g_csrc[MAXE];
__device__ int   g_blk[256];

__device__ __forceinline__ float leaky(float v) { return v > 0.f ? v : 0.1f * v; }

__device__ __forceinline__ uint32_t smem_u32(const void* p) {
    uint32_t a;
    asm("{ .reg .u64 t; cvta.to.shared.u64 t, %1; cvt.u32.u64 %0, t; }"
        : "=r"(a) : "l"(p));
    return a;
}

// smem tile: 128 rows x 64 bytes (32 bf16); chunk = 16B; swizzle keeps
// ldmatrix 8-lane phases and cp.async writes conflict-free.
__device__ __forceinline__ uint32_t swz(int row, int chunk) {
    return (uint32_t)(row * 64 + ((chunk ^ ((row ^ (row >> 2)) & 3)) * 16));
}

#define LDSM4(r, addr)                                                         \
    asm volatile("ldmatrix.sync.aligned.m8n8.x4.shared.b16 {%0,%1,%2,%3}, [%4];" \
                 : "=r"((r)[0]), "=r"((r)[1]), "=r"((r)[2]), "=r"((r)[3])      \
                 : "r"(addr))

#define MMA16(c, av, b0, b1)                                                   \
    asm volatile("mma.sync.aligned.m16n8k16.row.col.f32.bf16.bf16.f32 "        \
                 "{%0,%1,%2,%3}, {%4,%5,%6,%7}, {%8,%9}, {%0,%1,%2,%3};"       \
                 : "+f"((c)[0]), "+f"((c)[1]), "+f"((c)[2]), "+f"((c)[3])      \
                 : "r"((av)[0]), "r"((av)[1]), "r"((av)[2]), "r"((av)[3]),     \
                   "r"(b0), "r"(b1))

// ---------------------------------------------------------------------------
// bf16x3 warp-MMA GEMM: C[M,NOUT] = split(A[M,K]) @ split(B[NOUT,K])^T
// Block 128x128, BK=32, 256 thr (8 warps, 2x4), warp tile 64x32.
// DOTOUT: fuse out[r] += sum_col leaky(C[r,col]+bias[col]) * wout[col].
// ---------------------------------------------------------------------------
template <int K, bool LEAKY, bool DOTOUT>
__global__ __launch_bounds__(256, 2)
void mma_gemm(const bf16* __restrict__ Ah, const bf16* __restrict__ Al,
              const bf16* __restrict__ Bh, const bf16* __restrict__ Bl,
              const float* __restrict__ bias,
              bf16* __restrict__ Ch, bf16* __restrict__ Cl,
              const float* __restrict__ wout, float* __restrict__ dout,
              int NOUT, int MREAL) {
    extern __shared__ char sm[];
    const uint32_t sbase = smem_u32(sm);

    const int tid = threadIdx.x;
    const int lane = tid & 31, wid = tid >> 5;
    const int wm = wid >> 2, wn = wid & 3;        // 2 x 4 warp grid
    const int brow = blockIdx.y * 128;
    const int bcol = blockIdx.x * 128;

    float acc[4][4][4] = {};
    constexpr int NST = K / 32;

    // per-thread cp.async slots (2 chunks x 4 tiles), hoisted
    const int idx0 = tid * 2;                     // 0..510 within tile
    const int row0 = idx0 >> 2, c0 = idx0 & 3;
    const int row1 = (idx0 + 1) >> 2, c1 = (idx0 + 1) & 3;
    const uint32_t so0 = swz(row0, c0), so1 = swz(row1, c1);

    auto load_stage = [&](int s, int buf) {
        const int kofs = s * 32;
        const uint32_t sb = sbase + buf * 32768;
        const bf16* srcs[4] = {
            Ah + (size_t)brow * K + kofs, Al + (size_t)brow * K + kofs,
            Bh + (size_t)bcol * K + kofs, Bl + (size_t)bcol * K + kofs};
#pragma unroll
        for (int tile = 0; tile < 4; ++tile) {
            const bf16* base = srcs[tile];
            const uint32_t d = sb + tile * 8192;
            asm volatile("cp.async.cg.shared.global [%0], [%1], 16;"
                         :: "r"(d + so0), "l"(base + (size_t)row0 * K + c0 * 8));
            asm volatile("cp.async.cg.shared.global [%0], [%1], 16;"
                         :: "r"(d + so1), "l"(base + (size_t)row1 * K + c1 * 8));
        }
        asm volatile("cp.async.commit_group;" ::: "memory");
    };

    // ldmatrix address pieces (constant per thread across stages)
    const int arow_base = wm * 64 + (lane & 7) + ((lane >> 3) & 1) * 8;
    const int ach_half = lane >> 4;                       // 0/1
    const int brow_base = wn * 32 + ((lane >> 4) & 1) * 8 + (lane & 7);
    const int bch_half = (lane >> 3) & 1;                 // 0/1

    auto do_compute = [&](int buf) {
        const uint32_t sb = sbase + buf * 32768;
        const uint32_t Ahb = sb, Alb = sb + 8192;
        const uint32_t Bhb = sb + 16384, Blb = sb + 24576;
#pragma unroll
        for (int ks = 0; ks < 2; ++ks) {
            const int ach = ks * 2 + ach_half;
            const int bch = ks * 2 + bch_half;
            uint32_t a[4][4], bh[4][2], bl[4][2];
#pragma unroll
            for (int mi = 0; mi < 4; ++mi)
                LDSM4(a[mi], Ahb + swz(arow_base + mi * 16, ach));
#pragma unroll
            for (int p = 0; p < 2; ++p) {
                uint32_t r[4];
                LDSM4(r, Bhb + swz(brow_base + p * 16, bch));
                bh[p * 2][0] = r[0]; bh[p * 2][1] = r[1];
                bh[p * 2 + 1][0] = r[2]; bh[p * 2 + 1][1] = r[3];
            }
            // t0: Ah x Bh
#pragma unroll
            for (int mi = 0; mi < 4; ++mi)
#pragma unroll
                for (int ni = 0; ni < 4; ++ni)
                    MMA16(acc[mi][ni], a[mi], bh[ni][0], bh[ni][1]);
#pragma unroll
            for (int p = 0; p < 2; ++p) {
                uint32_t r[4];
                LDSM4(r, Blb + swz(brow_base + p * 16, bch));
                bl[p * 2][0] = r[0]; bl[p * 2][1] = r[1];
                bl[p * 2 + 1][0] = r[2]; bl[p * 2 + 1][1] = r[3];
            }
            // t1: Ah x Bl  (reuse a)
#pragma unroll
            for (int mi = 0; mi < 4; ++mi)
#pragma unroll
                for (int ni = 0; ni < 4; ++ni)
                    MMA16(acc[mi][ni], a[mi], bl[ni][0], bl[ni][1]);
            // Al fragments (overwrite a)
#pragma unroll
            for (int mi = 0; mi < 4; ++mi)
                LDSM4(a[mi], Alb + swz(arow_base + mi * 16, ach));
            // t2: Al x Bh  (reuse bh)
#pragma unroll
            for (int mi = 0; mi < 4; ++mi)
#pragma unroll
                for (int ni = 0; ni < 4; ++ni)
                    MMA16(acc[mi][ni], a[mi], bh[ni][0], bh[ni][1]);
        }
    };

    // 3-stage circular pipeline, loads run 2 stages ahead
    load_stage(0, 0);
    if (NST > 1) load_stage(1, 1);
    for (int s = 0; s < NST; ++s) {
        if (s + 1 < NST)
            asm volatile("cp.async.wait_group 1;" ::: "memory");
        else
            asm volatile("cp.async.wait_group 0;" ::: "memory");
        __syncthreads();
        if (s + 2 < NST) load_stage(s + 2, (s + 2) % 3);
        do_compute(s % 3);
    }

    // ---- epilogue ----
    if (DOTOUT) {
        float rs[4][2] = {};   // per (mi, h) partial row dots
#pragma unroll
        for (int mi = 0; mi < 4; ++mi) {
#pragma unroll
            for (int ni = 0; ni < 4; ++ni) {
                const int col = bcol + wn * 32 + ni * 8 + (lane & 3) * 2;
                const float2 bb = *(const float2*)&bias[col];
                const float2 wo = *(const float2*)&wout[col];
#pragma unroll
                for (int h = 0; h < 2; ++h) {
                    float v0 = acc[mi][ni][h * 2 + 0] + bb.x;
                    float v1 = acc[mi][ni][h * 2 + 1] + bb.y;
                    if (LEAKY) { v0 = leaky(v0); v1 = leaky(v1); }
                    rs[mi][h] += v0 * wo.x + v1 * wo.y;
                }
            }
        }
#pragma unroll
        for (int mi = 0; mi < 4; ++mi)
#pragma unroll
            for (int h = 0; h < 2; ++h) {
                rs[mi][h] += __shfl_xor_sync(0xFFFFFFFFu, rs[mi][h], 1);
                rs[mi][h] += __shfl_xor_sync(0xFFFFFFFFu, rs[mi][h], 2);
            }
        if ((lane & 3) == 0) {
            const int rbase = brow + wm * 64 + (lane >> 2);
#pragma unroll
            for (int mi = 0; mi < 4; ++mi)
#pragma unroll
                for (int h = 0; h < 2; ++h) {
                    const int r = rbase + mi * 16 + h * 8;
                    if (r < MREAL) atomicAdd(&dout[r], rs[mi][h]);
                }
        }
    } else {
#pragma unroll
        for (int mi = 0; mi < 4; ++mi) {
            const int r0 = brow + wm * 64 + mi * 16 + (lane >> 2);
#pragma unroll
            for (int ni = 0; ni < 4; ++ni) {
                const int col = bcol + wn * 32 + ni * 8 + (lane & 3) * 2;
                const float2 bb = *(const float2*)&bias[col];
#pragma unroll
                for (int h = 0; h < 2; ++h) {
                    const int r = r0 + h * 8;
                    float v0 = acc[mi][ni][h * 2 + 0] + bb.x;
                    float v1 = acc[mi][ni][h * 2 + 1] + bb.y;
                    if (LEAKY) { v0 = leaky(v0); v1 = leaky(v1); }
                    const __nv_bfloat162 hv = __floats2bfloat162_rn(v0, v1);
                    *(__nv_bfloat162*)&Ch[(size_t)r * NOUT + col] = hv;
                    const float l0 = v0 - __bfloat162float(hv.x);
                    const float l1 = v1 - __bfloat162float(hv.y);
                    *(__nv_bfloat162*)&Cl[(size_t)r * NOUT + col] =
                        __floats2bfloat162_rn(l0, l1);
                }
            }
        }
    }
}

// ---------------------------------------------------------------------------
// Prep (one kernel): weight transpose+split, out=b_out init, g_cnt zero
// ---------------------------------------------------------------------------
#define PW0 (DGCN * DIN)
#define PW1 (PW0 + HDIM * DGCN)
#define PW2 (PW1 + HDIM * HDIM)
#define PW3 (PW2 + HDIM * HDIM)
__global__ void prep_all(const float* __restrict__ Wg, const float* __restrict__ W1,
                         const float* __restrict__ W2, const float* __restrict__ W3,
                         const float* __restrict__ bout, float* __restrict__ out,
                         int n) {
    const int g = blockIdx.x * blockDim.x + threadIdx.x;
    if (g >= PW3) {
        const int i = g - PW3;
        if (i < n) {
            out[i] = bout[0];
            g_cnt[i] = 0;
        }
        return;
    }
    const float* W; bf16 *Th, *Tl; int K, NOUT, idx;
    if (g < PW0)      { W = Wg; Th = g_Wg_h; Tl = g_Wg_l; K = DIN;  NOUT = DGCN; idx = g; }
    else if (g < PW1) { W = W1; Th = g_W1_h; Tl = g_W1_l; K = DGCN; NOUT = HDIM; idx = g - PW0; }
    else if (g < PW2) { W = W2; Th = g_W2_h; Tl = g_W2_l; K = HDIM; NOUT = HDIM; idx = g - PW1; }
    else              { W = W3; Th = g_W3_h; Tl = g_W3_l; K = HDIM; NOUT = HDIM; idx = g - PW2; }
    const int n2 = idx / K, k = idx % K;
    const float v = W[(size_t)k * NOUT + n2];
    const bf16 h = __float2bfloat16(v);
    Th[idx] = h;
    Tl[idx] = __float2bfloat16(v - __bfloat162float(h));
}

// ---------------------------------------------------------------------------
// CSR build (no cursor; scatter bumps g_start, agg derives lo = end - cnt)
// ---------------------------------------------------------------------------
__global__ void hist_kernel(const int* __restrict__ dst, int E, int n) {
    int e = blockIdx.x * blockDim.x + threadIdx.x;
    if (e < E) {
        int d = dst[e];
        if ((unsigned)d < (unsigned)n) atomicAdd(&g_cnt[d], 1);
    }
}
__global__ void bsum_kernel(int n) {
    __shared__ int sh[256];
    const int b = blockIdx.x, t = threadIdx.x;
    const int i = b * 256 + t;
    sh[t] = (i < n) ? g_cnt[i] : 0;
    __syncthreads();
    for (int o = 128; o; o >>= 1) {
        if (t < o) sh[t] += sh[t + o];
        __syncthreads();
    }
    if (t == 0) g_blk[b] = sh[0];
}
__global__ void bscan_kernel(int nb) {
    __shared__ int sh[256];
    const int t = threadIdx.x;
    const int v = (t < nb) ? g_blk[t] : 0;
    sh[t] = v;
    __syncthreads();
    for (int o = 1; o < 256; o <<= 1) {
        int u = (t >= o) ? sh[t - o] : 0;
        __syncthreads();
        sh[t] += u;
        __syncthreads();
    }
    if (t < nb) g_blk[t] = sh[t] - v;  // exclusive
}
// exclusive scan finalize + dinv (fused)
__global__ void bfin_kernel(int n) {
    __shared__ int sh[256];
    const int b = blockIdx.x, t = threadIdx.x;
    const int i = b * 256 + t;
    const int v = (i < n) ? g_cnt[i] : 0;
    sh[t] = v;
    __syncthreads();
    for (int o = 1; o < 256; o <<= 1) {
        int u = (t >= o) ? sh[t - o] : 0;
        __syncthreads();
        sh[t] += u;
        __syncthreads();
    }
    if (i < n) {
        g_start[i] = g_blk[b] + sh[t] - v;
        g_dinv[i] = rsqrtf(1.0f + (float)v);
    }
}
__global__ void scatter_kernel(const int* __restrict__ src,
                               const int* __restrict__ dst, int E, int n) {
    int e = blockIdx.x * blockDim.x + threadIdx.x;
    if (e < E) {
        int d = dst[e], s = src[e];
        if ((unsigned)d >= (unsigned)n || (unsigned)s >= (unsigned)n) return;
        int pos = atomicAdd(&g_start[d], 1);
        g_csrc[pos] = s;
    }
}

// ---------------------------------------------------------------------------
// xs = S @ x: warp per node, lane = 4 cols (float4). Split bf16 output.
// After scatter, g_start[node] = segment END; lo = end - cnt.
// ---------------------------------------------------------------------------
__global__ __launch_bounds__(256)
void agg_warp_kernel(const float* __restrict__ x, int n) {
    const int node = (blockIdx.x * blockDim.x + threadIdx.x) >> 5;
    if (node >= n) return;
    const int lane = threadIdx.x & 31;
    const float di = g_dinv[node];
    float4 v = *(const float4*)&x[(size_t)node * DIN + lane * 4];
    float a0 = di * v.x, a1 = di * v.y, a2 = di * v.z, a3 = di * v.w;
    const int hi = g_start[node];
    const int lo = hi - g_cnt[node];
    for (int j = lo; j < hi; ++j) {
        const int s = g_csrc[j];
        const float ds = g_dinv[s];
        const float4 u = *(const float4*)&x[(size_t)s * DIN + lane * 4];
        a0 += ds * u.x; a1 += ds * u.y; a2 += ds * u.z; a3 += ds * u.w;
    }
    a0 *= di; a1 *= di; a2 *= di; a3 *= di;
    const size_t idx = (size_t)node * DIN + lane * 4;
    const __nv_bfloat162 h01 = __floats2bfloat162_rn(a0, a1);
    const __nv_bfloat162 h23 = __floats2bfloat162_rn(a2, a3);
    *(__nv_bfloat162*)&g_xs_h[idx] = h01;
    *(__nv_bfloat162*)&g_xs_h[idx + 2] = h23;
    *(__nv_bfloat162*)&g_xs_l[idx] = __floats2bfloat162_rn(
        a0 - __bfloat162float(h01.x), a1 - __bfloat162float(h01.y));
    *(__nv_bfloat162*)&g_xs_l[idx + 2] = __floats2bfloat162_rn(
        a2 - __bfloat162float(h23.x), a3 - __bfloat162float(h23.y));
}

// ---------------------------------------------------------------------------
// Launch
// ---------------------------------------------------------------------------
extern "C" void kernel_launch(void* const* d_in, const int* in_sizes, int n_in,
                              void* d_out, int out_size) {
    const float* x     = (const float*)d_in[0];
    const int*   ei    = (const int*)d_in[1];
    const float* W_gcn = (const float*)d_in[2];
    const float* b_gcn = (const float*)d_in[3];
    const float* W1    = (const float*)d_in[4];
    const float* b1    = (const float*)d_in[5];
    const float* W2    = (const float*)d_in[6];
    const float* b2    = (const float*)d_in[7];
    const float* W3    = (const float*)d_in[8];
    const float* b3    = (const float*)d_in[9];
    const float* Wout  = (const float*)d_in[10];
    const float* bout  = (const float*)d_in[11];
    float* out = (float*)d_out;

    const int N = in_sizes[0] / DIN;
    const int E = in_sizes[1] / 2;
    const int* src = ei;
    const int* dst = ei + E;
    const int nb = DIV_UP(N, 256);

    bf16 *p_xs_h, *p_xs_l, *p_ag_h, *p_ag_l, *p_h1_h, *p_h1_l, *p_h2_h, *p_h2_l;
    bf16 *p_Wg_h, *p_Wg_l, *p_W1_h, *p_W1_l, *p_W2_h, *p_W2_l, *p_W3_h, *p_W3_l;
    cudaGetSymbolAddress((void**)&p_xs_h, g_xs_h);
    cudaGetSymbolAddress((void**)&p_xs_l, g_xs_l);
    cudaGetSymbolAddress((void**)&p_ag_h, g_ag_h);
    cudaGetSymbolAddress((void**)&p_ag_l, g_ag_l);
    cudaGetSymbolAddress((void**)&p_h1_h, g_h1_h);
    cudaGetSymbolAddress((void**)&p_h1_l, g_h1_l);
    cudaGetSymbolAddress((void**)&p_h2_h, g_h2_h);
    cudaGetSymbolAddress((void**)&p_h2_l, g_h2_l);
    cudaGetSymbolAddress((void**)&p_Wg_h, g_Wg_h);
    cudaGetSymbolAddress((void**)&p_Wg_l, g_Wg_l);
    cudaGetSymbolAddress((void**)&p_W1_h, g_W1_h);
    cudaGetSymbolAddress((void**)&p_W1_l, g_W1_l);
    cudaGetSymbolAddress((void**)&p_W2_h, g_W2_h);
    cudaGetSymbolAddress((void**)&p_W2_l, g_W2_l);
    cudaGetSymbolAddress((void**)&p_W3_h, g_W3_h);
    cudaGetSymbolAddress((void**)&p_W3_l, g_W3_l);

    const int SMEM = 98304;  // 3 stages x 32KB
    cudaFuncSetAttribute(mma_gemm<128, false, false>,
                         cudaFuncAttributeMaxDynamicSharedMemorySize, SMEM);
    cudaFuncSetAttribute(mma_gemm<512, true, false>,
                         cudaFuncAttributeMaxDynamicSharedMemorySize, SMEM);
    cudaFuncSetAttribute(mma_gemm<256, true, false>,
                         cudaFuncAttributeMaxDynamicSharedMemorySize, SMEM);
    cudaFuncSetAttribute(mma_gemm<256, true, true>,
                         cudaFuncAttributeMaxDynamicSharedMemorySize, SMEM);

    // prep: weights + out=b_out + g_cnt=0
    prep_all<<<DIV_UP(PW3 + N, 256), 256>>>(W_gcn, W1, W2, W3, bout, out, N);

    // CSR build + norms
    hist_kernel<<<DIV_UP(E, 256), 256>>>(dst, E, N);
    bsum_kernel<<<nb, 256>>>(N);
    bscan_kernel<<<1, 256>>>(nb);
    bfin_kernel<<<nb, 256>>>(N);   // also computes g_dinv
    scatter_kernel<<<DIV_UP(E, 256), 256>>>(src, dst, E, N);

    // xs = S @ x  (split bf16 output), warp per node
    agg_warp_kernel<<<DIV_UP(N * 32, 256), 256>>>(x, N);

    const int mt = DIV_UP(N, 128);
    mma_gemm<128, false, false><<<dim3(DGCN / 128, mt), 256, SMEM>>>(
        p_xs_h, p_xs_l, p_Wg_h, p_Wg_l, b_gcn, p_ag_h, p_ag_l,
        nullptr, nullptr, DGCN, N);
    mma_gemm<512, true, false><<<dim3(HDIM / 128, mt), 256, SMEM>>>(
        p_ag_h, p_ag_l, p_W1_h, p_W1_l, b1, p_h1_h, p_h1_l,
        nullptr, nullptr, HDIM, N);
    mma_gemm<256, true, false><<<dim3(HDIM / 128, mt), 256, SMEM>>>(
        p_h1_h, p_h1_l, p_W2_h, p_W2_l, b2, p_h2_h, p_h2_l,
        nullptr, nullptr, HDIM, N);
    // GEMM4 + fused W_out dot -> out
    mma_gemm<256, true, true><<<dim3(HDIM / 128, mt), 256, SMEM>>>(
        p_h2_h, p_h2_l, p_W3_h, p_W3_l, b3, nullptr, nullptr,
        Wout, out, HDIM, N);
}

// round 12
// speedup vs baseline: 6.9332x; 1.3774x over previous
#include <cuda_runtime.h>
#include <cuda_bf16.h>
#include <stdint.h>

// ---------------------------------------------------------------------------
// N=50000, D=128, GCN out=512, H=256, E=800000. edge_index int32.
// Key algebra: no nonlinearity between GCN and W1 =>
//   h1 = leaky(xs @ (W_gcn@W1) + (b_gcn@W1 + b1)),  xs = S @ x (CSR agg).
// 3 GEMMs total (K=128,256,256; NOUT=256), mma.sync bf16x3 split,
// final W_out dot fused into last GEMM epilogue.
// ---------------------------------------------------------------------------
#define MAXN  50000
#define MAXNP 50048      // multiple of 128; padded rows are zero
#define MAXE  800000
#define DIN   128
#define DGCN  512
#define HDIM  256
#define DIV_UP(a, b) (((a) + (b) - 1) / (b))

typedef __nv_bfloat16 bf16;

// ---- scratch (device globals; zero-initialized at module load) ----
__device__ bf16  g_xs_h[(size_t)MAXNP * DIN],  g_xs_l[(size_t)MAXNP * DIN];
__device__ bf16  g_h1_h[(size_t)MAXNP * HDIM], g_h1_l[(size_t)MAXNP * HDIM];
__device__ bf16  g_h2_h[(size_t)MAXNP * HDIM], g_h2_l[(size_t)MAXNP * HDIM];
// combined + split weights [NOUT, K]
__device__ bf16  g_Wc_h[HDIM * DIN],  g_Wc_l[HDIM * DIN];   // (W_gcn@W1)^T split
__device__ float g_bc[HDIM];                                 // b_gcn@W1 + b1
__device__ bf16  g_W2_h[HDIM * HDIM], g_W2_l[HDIM * HDIM];
__device__ bf16  g_W3_h[HDIM * HDIM], g_W3_l[HDIM * HDIM];
// graph
__device__ float g_dinv[MAXN];
__device__ int   g_cnt[MAXN], g_start[MAXN], g_csrc[MAXE];
__device__ int   g_blk[256];

__device__ __forceinline__ float leaky(float v) { return v > 0.f ? v : 0.1f * v; }

__device__ __forceinline__ uint32_t smem_u32(const void* p) {
    uint32_t a;
    asm("{ .reg .u64 t; cvta.to.shared.u64 t, %1; cvt.u32.u64 %0, t; }"
        : "=r"(a) : "l"(p));
    return a;
}

// smem tile: 128 rows x 64 bytes (32 bf16); chunk = 16B; swizzle keeps
// ldmatrix 8-lane phases and cp.async writes conflict-free.
__device__ __forceinline__ uint32_t swz(int row, int chunk) {
    return (uint32_t)(row * 64 + ((chunk ^ ((row ^ (row >> 2)) & 3)) * 16));
}

#define LDSM4(r, addr)                                                         \
    asm volatile("ldmatrix.sync.aligned.m8n8.x4.shared.b16 {%0,%1,%2,%3}, [%4];" \
                 : "=r"((r)[0]), "=r"((r)[1]), "=r"((r)[2]), "=r"((r)[3])      \
                 : "r"(addr))

#define MMA16(c, av, b0, b1)                                                   \
    asm volatile("mma.sync.aligned.m16n8k16.row.col.f32.bf16.bf16.f32 "        \
                 "{%0,%1,%2,%3}, {%4,%5,%6,%7}, {%8,%9}, {%0,%1,%2,%3};"       \
                 : "+f"((c)[0]), "+f"((c)[1]), "+f"((c)[2]), "+f"((c)[3])      \
                 : "r"((av)[0]), "r"((av)[1]), "r"((av)[2]), "r"((av)[3]),     \
                   "r"(b0), "r"(b1))

// ---------------------------------------------------------------------------
// bf16x3 warp-MMA GEMM: C[M,NOUT] = split(A[M,K]) @ split(B[NOUT,K])^T
// Block 128x128, BK=32, 256 thr (8 warps, 2x4), warp tile 64x32.
// DOTOUT: fuse out[r] += sum_col leaky(C[r,col]+bias[col]) * wout[col].
// ---------------------------------------------------------------------------
template <int K, bool LEAKY, bool DOTOUT>
__global__ __launch_bounds__(256, 2)
void mma_gemm(const bf16* __restrict__ Ah, const bf16* __restrict__ Al,
              const bf16* __restrict__ Bh, const bf16* __restrict__ Bl,
              const float* __restrict__ bias,
              bf16* __restrict__ Ch, bf16* __restrict__ Cl,
              const float* __restrict__ wout, float* __restrict__ dout,
              int NOUT, int MREAL) {
    extern __shared__ char sm[];
    const uint32_t sbase = smem_u32(sm);

    const int tid = threadIdx.x;
    const int lane = tid & 31, wid = tid >> 5;
    const int wm = wid >> 2, wn = wid & 3;        // 2 x 4 warp grid
    const int brow = blockIdx.y * 128;
    const int bcol = blockIdx.x * 128;

    float acc[4][4][4] = {};
    constexpr int NST = K / 32;

    // per-thread cp.async slots (2 chunks x 4 tiles), hoisted
    const int idx0 = tid * 2;                     // 0..510 within tile
    const int row0 = idx0 >> 2, c0 = idx0 & 3;
    const int row1 = (idx0 + 1) >> 2, c1 = (idx0 + 1) & 3;
    const uint32_t so0 = swz(row0, c0), so1 = swz(row1, c1);

    auto load_stage = [&](int s, int buf) {
        const int kofs = s * 32;
        const uint32_t sb = sbase + buf * 32768;
        const bf16* srcs[4] = {
            Ah + (size_t)brow * K + kofs, Al + (size_t)brow * K + kofs,
            Bh + (size_t)bcol * K + kofs, Bl + (size_t)bcol * K + kofs};
#pragma unroll
        for (int tile = 0; tile < 4; ++tile) {
            const bf16* base = srcs[tile];
            const uint32_t d = sb + tile * 8192;
            asm volatile("cp.async.cg.shared.global [%0], [%1], 16;"
                         :: "r"(d + so0), "l"(base + (size_t)row0 * K + c0 * 8));
            asm volatile("cp.async.cg.shared.global [%0], [%1], 16;"
                         :: "r"(d + so1), "l"(base + (size_t)row1 * K + c1 * 8));
        }
        asm volatile("cp.async.commit_group;" ::: "memory");
    };

    // ldmatrix address pieces (constant per thread across stages)
    const int arow_base = wm * 64 + (lane & 7) + ((lane >> 3) & 1) * 8;
    const int ach_half = lane >> 4;                       // 0/1
    const int brow_base = wn * 32 + ((lane >> 4) & 1) * 8 + (lane & 7);
    const int bch_half = (lane >> 3) & 1;                 // 0/1

    auto do_compute = [&](int buf) {
        const uint32_t sb = sbase + buf * 32768;
        const uint32_t Ahb = sb, Alb = sb + 8192;
        const uint32_t Bhb = sb + 16384, Blb = sb + 24576;
#pragma unroll
        for (int ks = 0; ks < 2; ++ks) {
            const int ach = ks * 2 + ach_half;
            const int bch = ks * 2 + bch_half;
            uint32_t a[4][4], bh[4][2], bl[4][2];
#pragma unroll
            for (int mi = 0; mi < 4; ++mi)
                LDSM4(a[mi], Ahb + swz(arow_base + mi * 16, ach));
#pragma unroll
            for (int p = 0; p < 2; ++p) {
                uint32_t r[4];
                LDSM4(r, Bhb + swz(brow_base + p * 16, bch));
                bh[p * 2][0] = r[0]; bh[p * 2][1] = r[1];
                bh[p * 2 + 1][0] = r[2]; bh[p * 2 + 1][1] = r[3];
            }
            // t0: Ah x Bh
#pragma unroll
            for (int mi = 0; mi < 4; ++mi)
#pragma unroll
                for (int ni = 0; ni < 4; ++ni)
                    MMA16(acc[mi][ni], a[mi], bh[ni][0], bh[ni][1]);
#pragma unroll
            for (int p = 0; p < 2; ++p) {
                uint32_t r[4];
                LDSM4(r, Blb + swz(brow_base + p * 16, bch));
                bl[p * 2][0] = r[0]; bl[p * 2][1] = r[1];
                bl[p * 2 + 1][0] = r[2]; bl[p * 2 + 1][1] = r[3];
            }
            // t1: Ah x Bl  (reuse a)
#pragma unroll
            for (int mi = 0; mi < 4; ++mi)
#pragma unroll
                for (int ni = 0; ni < 4; ++ni)
                    MMA16(acc[mi][ni], a[mi], bl[ni][0], bl[ni][1]);
            // Al fragments (overwrite a)
#pragma unroll
            for (int mi = 0; mi < 4; ++mi)
                LDSM4(a[mi], Alb + swz(arow_base + mi * 16, ach));
            // t2: Al x Bh  (reuse bh)
#pragma unroll
            for (int mi = 0; mi < 4; ++mi)
#pragma unroll
                for (int ni = 0; ni < 4; ++ni)
                    MMA16(acc[mi][ni], a[mi], bh[ni][0], bh[ni][1]);
        }
    };

    // 3-stage circular pipeline, loads run 2 stages ahead
    load_stage(0, 0);
    if (NST > 1) load_stage(1, 1);
    for (int s = 0; s < NST; ++s) {
        if (s + 1 < NST)
            asm volatile("cp.async.wait_group 1;" ::: "memory");
        else
            asm volatile("cp.async.wait_group 0;" ::: "memory");
        __syncthreads();
        if (s + 2 < NST) load_stage(s + 2, (s + 2) % 3);
        do_compute(s % 3);
    }

    // ---- epilogue ----
    if (DOTOUT) {
        float rs[4][2] = {};   // per (mi, h) partial row dots
#pragma unroll
        for (int mi = 0; mi < 4; ++mi) {
#pragma unroll
            for (int ni = 0; ni < 4; ++ni) {
                const int col = bcol + wn * 32 + ni * 8 + (lane & 3) * 2;
                const float2 bb = *(const float2*)&bias[col];
                const float2 wo = *(const float2*)&wout[col];
#pragma unroll
                for (int h = 0; h < 2; ++h) {
                    float v0 = acc[mi][ni][h * 2 + 0] + bb.x;
                    float v1 = acc[mi][ni][h * 2 + 1] + bb.y;
                    if (LEAKY) { v0 = leaky(v0); v1 = leaky(v1); }
                    rs[mi][h] += v0 * wo.x + v1 * wo.y;
                }
            }
        }
#pragma unroll
        for (int mi = 0; mi < 4; ++mi)
#pragma unroll
            for (int h = 0; h < 2; ++h) {
                rs[mi][h] += __shfl_xor_sync(0xFFFFFFFFu, rs[mi][h], 1);
                rs[mi][h] += __shfl_xor_sync(0xFFFFFFFFu, rs[mi][h], 2);
            }
        if ((lane & 3) == 0) {
            const int rbase = brow + wm * 64 + (lane >> 2);
#pragma unroll
            for (int mi = 0; mi < 4; ++mi)
#pragma unroll
                for (int h = 0; h < 2; ++h) {
                    const int r = rbase + mi * 16 + h * 8;
                    if (r < MREAL) atomicAdd(&dout[r], rs[mi][h]);
                }
        }
    } else {
#pragma unroll
        for (int mi = 0; mi < 4; ++mi) {
            const int r0 = brow + wm * 64 + mi * 16 + (lane >> 2);
#pragma unroll
            for (int ni = 0; ni < 4; ++ni) {
                const int col = bcol + wn * 32 + ni * 8 + (lane & 3) * 2;
                const float2 bb = *(const float2*)&bias[col];
#pragma unroll
                for (int h = 0; h < 2; ++h) {
                    const int r = r0 + h * 8;
                    float v0 = acc[mi][ni][h * 2 + 0] + bb.x;
                    float v1 = acc[mi][ni][h * 2 + 1] + bb.y;
                    if (LEAKY) { v0 = leaky(v0); v1 = leaky(v1); }
                    const __nv_bfloat162 hv = __floats2bfloat162_rn(v0, v1);
                    *(__nv_bfloat162*)&Ch[(size_t)r * NOUT + col] = hv;
                    const float l0 = v0 - __bfloat162float(hv.x);
                    const float l1 = v1 - __bfloat162float(hv.y);
                    *(__nv_bfloat162*)&Cl[(size_t)r * NOUT + col] =
                        __floats2bfloat162_rn(l0, l1);
                }
            }
        }
    }
}

// ---------------------------------------------------------------------------
// Wc = W_gcn @ W1  ([128,512]@[512,256] -> [128,256]), stored transposed+split.
// One block per k-row of W_gcn (cached in smem), 256 threads = output cols.
// ---------------------------------------------------------------------------
__global__ __launch_bounds__(256)
void wc_kernel(const float* __restrict__ Wg, const float* __restrict__ W1) {
    __shared__ float row[DGCN];
    const int k = blockIdx.x;          // 0..127
    const int n = threadIdx.x;         // 0..255
    row[n] = Wg[(size_t)k * DGCN + n];
    row[n + 256] = Wg[(size_t)k * DGCN + n + 256];
    __syncthreads();
    float acc = 0.f;
#pragma unroll 8
    for (int j = 0; j < DGCN; ++j)
        acc += row[j] * W1[(size_t)j * HDIM + n];
    const bf16 h = __float2bfloat16(acc);
    g_Wc_h[n * DIN + k] = h;
    g_Wc_l[n * DIN + k] = __float2bfloat16(acc - __bfloat162float(h));
}

// bc = b_gcn @ W1 + b1   (256 threads)
__global__ void bc_kernel(const float* __restrict__ bg, const float* __restrict__ W1,
                          const float* __restrict__ b1) {
    const int n = threadIdx.x;
    float acc = b1[n];
#pragma unroll 8
    for (int j = 0; j < DGCN; ++j)
        acc += bg[j] * W1[(size_t)j * HDIM + n];
    g_bc[n] = acc;
}

// ---------------------------------------------------------------------------
// Prep (one kernel): W2/W3 transpose+split, out=b_out init, g_cnt zero
// ---------------------------------------------------------------------------
#define PW0 (HDIM * HDIM)
#define PW1 (2 * HDIM * HDIM)
__global__ void prep_all(const float* __restrict__ W2, const float* __restrict__ W3,
                         const float* __restrict__ bout, float* __restrict__ out,
                         int n) {
    const int g = blockIdx.x * blockDim.x + threadIdx.x;
    if (g >= PW1) {
        const int i = g - PW1;
        if (i < n) {
            out[i] = bout[0];
            g_cnt[i] = 0;
        }
        return;
    }
    const float* W; bf16 *Th, *Tl; int idx;
    if (g < PW0) { W = W2; Th = g_W2_h; Tl = g_W2_l; idx = g; }
    else         { W = W3; Th = g_W3_h; Tl = g_W3_l; idx = g - PW0; }
    const int n2 = idx / HDIM, k = idx % HDIM;
    const float v = W[(size_t)k * HDIM + n2];
    const bf16 h = __float2bfloat16(v);
    Th[idx] = h;
    Tl[idx] = __float2bfloat16(v - __bfloat162float(h));
}

// ---------------------------------------------------------------------------
// CSR build (no cursor; scatter bumps g_start, agg derives lo = end - cnt)
// ---------------------------------------------------------------------------
__global__ void hist_kernel(const int* __restrict__ dst, int E, int n) {
    int e = blockIdx.x * blockDim.x + threadIdx.x;
    if (e < E) {
        int d = dst[e];
        if ((unsigned)d < (unsigned)n) atomicAdd(&g_cnt[d], 1);
    }
}
__global__ void bsum_kernel(int n) {
    __shared__ int sh[256];
    const int b = blockIdx.x, t = threadIdx.x;
    const int i = b * 256 + t;
    sh[t] = (i < n) ? g_cnt[i] : 0;
    __syncthreads();
    for (int o = 128; o; o >>= 1) {
        if (t < o) sh[t] += sh[t + o];
        __syncthreads();
    }
    if (t == 0) g_blk[b] = sh[0];
}
__global__ void bscan_kernel(int nb) {
    __shared__ int sh[256];
    const int t = threadIdx.x;
    const int v = (t < nb) ? g_blk[t] : 0;
    sh[t] = v;
    __syncthreads();
    for (int o = 1; o < 256; o <<= 1) {
        int u = (t >= o) ? sh[t - o] : 0;
        __syncthreads();
        sh[t] += u;
        __syncthreads();
    }
    if (t < nb) g_blk[t] = sh[t] - v;  // exclusive
}
// exclusive scan finalize + dinv (fused)
__global__ void bfin_kernel(int n) {
    __shared__ int sh[256];
    const int b = blockIdx.x, t = threadIdx.x;
    const int i = b * 256 + t;
    const int v = (i < n) ? g_cnt[i] : 0;
    sh[t] = v;
    __syncthreads();
    for (int o = 1; o < 256; o <<= 1) {
        int u = (t >= o) ? sh[t - o] : 0;
        __syncthreads();
        sh[t] += u;
        __syncthreads();
    }
    if (i < n) {
        g_start[i] = g_blk[b] + sh[t] - v;
        g_dinv[i] = rsqrtf(1.0f + (float)v);
    }
}
__global__ void scatter_kernel(const int* __restrict__ src,
                               const int* __restrict__ dst, int E, int n) {
    int e = blockIdx.x * blockDim.x + threadIdx.x;
    if (e < E) {
        int d = dst[e], s = src[e];
        if ((unsigned)d >= (unsigned)n || (unsigned)s >= (unsigned)n) return;
        int pos = atomicAdd(&g_start[d], 1);
        g_csrc[pos] = s;
    }
}

// ---------------------------------------------------------------------------
// xs = S @ x: warp per node, lane = 4 cols (float4). Split bf16 output.
// After scatter, g_start[node] = segment END; lo = end - cnt.
// ---------------------------------------------------------------------------
__global__ __launch_bounds__(256)
void agg_warp_kernel(const float* __restrict__ x, int n) {
    const int node = (blockIdx.x * blockDim.x + threadIdx.x) >> 5;
    if (node >= n) return;
    const int lane = threadIdx.x & 31;
    const float di = g_dinv[node];
    float4 v = *(const float4*)&x[(size_t)node * DIN + lane * 4];
    float a0 = di * v.x, a1 = di * v.y, a2 = di * v.z, a3 = di * v.w;
    const int hi = g_start[node];
    const int lo = hi - g_cnt[node];
    for (int j = lo; j < hi; ++j) {
        const int s = g_csrc[j];
        const float ds = g_dinv[s];
        const float4 u = *(const float4*)&x[(size_t)s * DIN + lane * 4];
        a0 += ds * u.x; a1 += ds * u.y; a2 += ds * u.z; a3 += ds * u.w;
    }
    a0 *= di; a1 *= di; a2 *= di; a3 *= di;
    const size_t idx = (size_t)node * DIN + lane * 4;
    const __nv_bfloat162 h01 = __floats2bfloat162_rn(a0, a1);
    const __nv_bfloat162 h23 = __floats2bfloat162_rn(a2, a3);
    *(__nv_bfloat162*)&g_xs_h[idx] = h01;
    *(__nv_bfloat162*)&g_xs_h[idx + 2] = h23;
    *(__nv_bfloat162*)&g_xs_l[idx] = __floats2bfloat162_rn(
        a0 - __bfloat162float(h01.x), a1 - __bfloat162float(h01.y));
    *(__nv_bfloat162*)&g_xs_l[idx + 2] = __floats2bfloat162_rn(
        a2 - __bfloat162float(h23.x), a3 - __bfloat162float(h23.y));
}

// ---------------------------------------------------------------------------
// Launch
// ---------------------------------------------------------------------------
extern "C" void kernel_launch(void* const* d_in, const int* in_sizes, int n_in,
                              void* d_out, int out_size) {
    const float* x     = (const float*)d_in[0];
    const int*   ei    = (const int*)d_in[1];
    const float* W_gcn = (const float*)d_in[2];
    const float* b_gcn = (const float*)d_in[3];
    const float* W1    = (const float*)d_in[4];
    const float* b1    = (const float*)d_in[5];
    const float* W2    = (const float*)d_in[6];
    const float* b2    = (const float*)d_in[7];
    const float* W3    = (const float*)d_in[8];
    const float* b3    = (const float*)d_in[9];
    const float* Wout  = (const float*)d_in[10];
    const float* bout  = (const float*)d_in[11];
    float* out = (float*)d_out;

    const int N = in_sizes[0] / DIN;
    const int E = in_sizes[1] / 2;
    const int* src = ei;
    const int* dst = ei + E;
    const int nb = DIV_UP(N, 256);

    bf16 *p_xs_h, *p_xs_l, *p_h1_h, *p_h1_l, *p_h2_h, *p_h2_l;
    bf16 *p_Wc_h, *p_Wc_l, *p_W2_h, *p_W2_l, *p_W3_h, *p_W3_l;
    float* p_bc;
    cudaGetSymbolAddress((void**)&p_xs_h, g_xs_h);
    cudaGetSymbolAddress((void**)&p_xs_l, g_xs_l);
    cudaGetSymbolAddress((void**)&p_h1_h, g_h1_h);
    cudaGetSymbolAddress((void**)&p_h1_l, g_h1_l);
    cudaGetSymbolAddress((void**)&p_h2_h, g_h2_h);
    cudaGetSymbolAddress((void**)&p_h2_l, g_h2_l);
    cudaGetSymbolAddress((void**)&p_Wc_h, g_Wc_h);
    cudaGetSymbolAddress((void**)&p_Wc_l, g_Wc_l);
    cudaGetSymbolAddress((void**)&p_W2_h, g_W2_h);
    cudaGetSymbolAddress((void**)&p_W2_l, g_W2_l);
    cudaGetSymbolAddress((void**)&p_W3_h, g_W3_h);
    cudaGetSymbolAddress((void**)&p_W3_l, g_W3_l);
    cudaGetSymbolAddress((void**)&p_bc, g_bc);

    const int SMEM = 98304;  // 3 stages x 32KB
    cudaFuncSetAttribute(mma_gemm<128, true, false>,
                         cudaFuncAttributeMaxDynamicSharedMemorySize, SMEM);
    cudaFuncSetAttribute(mma_gemm<256, true, false>,
                         cudaFuncAttributeMaxDynamicSharedMemorySize, SMEM);
    cudaFuncSetAttribute(mma_gemm<256, true, true>,
                         cudaFuncAttributeMaxDynamicSharedMemorySize, SMEM);

    // prep: W2/W3 split + out=b_out + g_cnt=0; Wc = W_gcn@W1; bc
    prep_all<<<DIV_UP(PW1 + N, 256), 256>>>(W2, W3, bout, out, N);
    wc_kernel<<<DIN, 256>>>(W_gcn, W1);
    bc_kernel<<<1, 256>>>(b_gcn, W1, b1);

    // CSR build + norms
    hist_kernel<<<DIV_UP(E, 256), 256>>>(dst, E, N);
    bsum_kernel<<<nb, 256>>>(N);
    bscan_kernel<<<1, 256>>>(nb);
    bfin_kernel<<<nb, 256>>>(N);   // also computes g_dinv
    scatter_kernel<<<DIV_UP(E, 256), 256>>>(src, dst, E, N);

    // xs = S @ x  (split bf16 output), warp per node
    agg_warp_kernel<<<DIV_UP(N * 32, 256), 256>>>(x, N);

    const int mt = DIV_UP(N, 128);
    const dim3 grid(HDIM / 128, mt);
    // h1 = leaky(xs @ Wc + bc)
    mma_gemm<128, true, false><<<grid, 256, SMEM>>>(
        p_xs_h, p_xs_l, p_Wc_h, p_Wc_l, p_bc, p_h1_h, p_h1_l,
        nullptr, nullptr, HDIM, N);
    // h2 = leaky(h1 @ W2 + b2)
    mma_gemm<256, true, false><<<grid, 256, SMEM>>>(
        p_h1_h, p_h1_l, p_W2_h, p_W2_l, b2, p_h2_h, p_h2_l,
        nullptr, nullptr, HDIM, N);
    // out += leaky(h2 @ W3 + b3) . Wout   (fused)
    mma_gemm<256, true, true><<<grid, 256, SMEM>>>(
        p_h2_h, p_h2_l, p_W3_h, p_W3_l, b3, nullptr, nullptr,
        Wout, out, HDIM, N);
}

// round 13
// speedup vs baseline: 7.2208x; 1.0415x over previous
#include <cuda_runtime.h>
#include <cuda_bf16.h>
#include <stdint.h>

// ---------------------------------------------------------------------------
// N=50000, D=128, GCN out=512, H=256, E=800000. edge_index int32.
// h1 = leaky(xs @ (W_gcn@W1) + (b_gcn@W1 + b1)),  xs = S @ x.
// Graph agg via linked-list buckets (1 scatter kernel, no prefix sums).
// 3 GEMMs (K=128,256,256), mma.sync bf16x3 split, W_out dot fused in GEMM3.
// ---------------------------------------------------------------------------
#define MAXN  50000
#define MAXNP 50048      // multiple of 128; padded rows are zero
#define MAXE  800000
#define DIN   128
#define DGCN  512
#define HDIM  256
#define DIV_UP(a, b) (((a) + (b) - 1) / (b))

typedef __nv_bfloat16 bf16;

// ---- scratch (device globals; zero-initialized at module load) ----
__device__ bf16  g_xs_h[(size_t)MAXNP * DIN],  g_xs_l[(size_t)MAXNP * DIN];
__device__ bf16  g_h1_h[(size_t)MAXNP * HDIM], g_h1_l[(size_t)MAXNP * HDIM];
__device__ bf16  g_h2_h[(size_t)MAXNP * HDIM], g_h2_l[(size_t)MAXNP * HDIM];
// combined + split weights [NOUT, K]
__device__ bf16  g_Wc_h[HDIM * DIN],  g_Wc_l[HDIM * DIN];   // (W_gcn@W1)^T split
__device__ float g_bc[HDIM];                                 // b_gcn@W1 + b1
__device__ bf16  g_W2_h[HDIM * HDIM], g_W2_l[HDIM * HDIM];
__device__ bf16  g_W3_h[HDIM * HDIM], g_W3_l[HDIM * HDIM];
// graph (linked-list buckets)
__device__ int g_head[MAXN], g_cnt[MAXN], g_link[MAXE];

__device__ __forceinline__ float leaky(float v) { return v > 0.f ? v : 0.1f * v; }

__device__ __forceinline__ uint32_t smem_u32(const void* p) {
    uint32_t a;
    asm("{ .reg .u64 t; cvta.to.shared.u64 t, %1; cvt.u32.u64 %0, t; }"
        : "=r"(a) : "l"(p));
    return a;
}

// smem tile: 128 rows x 64 bytes (32 bf16); chunk = 16B; swizzle keeps
// ldmatrix 8-lane phases and cp.async writes conflict-free.
__device__ __forceinline__ uint32_t swz(int row, int chunk) {
    return (uint32_t)(row * 64 + ((chunk ^ ((row ^ (row >> 2)) & 3)) * 16));
}

#define LDSM4(r, addr)                                                         \
    asm volatile("ldmatrix.sync.aligned.m8n8.x4.shared.b16 {%0,%1,%2,%3}, [%4];" \
                 : "=r"((r)[0]), "=r"((r)[1]), "=r"((r)[2]), "=r"((r)[3])      \
                 : "r"(addr))

#define MMA16(c, av, b0, b1)                                                   \
    asm volatile("mma.sync.aligned.m16n8k16.row.col.f32.bf16.bf16.f32 "        \
                 "{%0,%1,%2,%3}, {%4,%5,%6,%7}, {%8,%9}, {%0,%1,%2,%3};"       \
                 : "+f"((c)[0]), "+f"((c)[1]), "+f"((c)[2]), "+f"((c)[3])      \
                 : "r"((av)[0]), "r"((av)[1]), "r"((av)[2]), "r"((av)[3]),     \
                   "r"(b0), "r"(b1))

// ---------------------------------------------------------------------------
// bf16x3 warp-MMA GEMM: C[M,NOUT] = split(A[M,K]) @ split(B[NOUT,K])^T
// Block 128x128, BK=32, 256 thr (8 warps, 2x4), warp tile 64x32.
// DOTOUT: fuse out[r] += sum_col leaky(C[r,col]+bias[col]) * wout[col].
// ---------------------------------------------------------------------------
template <int K, bool LEAKY, bool DOTOUT>
__global__ __launch_bounds__(256, 2)
void mma_gemm(const bf16* __restrict__ Ah, const bf16* __restrict__ Al,
              const bf16* __restrict__ Bh, const bf16* __restrict__ Bl,
              const float* __restrict__ bias,
              bf16* __restrict__ Ch, bf16* __restrict__ Cl,
              const float* __restrict__ wout, float* __restrict__ dout,
              int NOUT, int MREAL) {
    extern __shared__ char sm[];
    const uint32_t sbase = smem_u32(sm);

    const int tid = threadIdx.x;
    const int lane = tid & 31, wid = tid >> 5;
    const int wm = wid >> 2, wn = wid & 3;        // 2 x 4 warp grid
    const int brow = blockIdx.y * 128;
    const int bcol = blockIdx.x * 128;

    float acc[4][4][4] = {};
    constexpr int NST = K / 32;

    // per-thread cp.async slots (2 chunks x 4 tiles), hoisted
    const int idx0 = tid * 2;                     // 0..510 within tile
    const int row0 = idx0 >> 2, c0 = idx0 & 3;
    const int row1 = (idx0 + 1) >> 2, c1 = (idx0 + 1) & 3;
    const uint32_t so0 = swz(row0, c0), so1 = swz(row1, c1);

    auto load_stage = [&](int s, int buf) {
        const int kofs = s * 32;
        const uint32_t sb = sbase + buf * 32768;
        const bf16* srcs[4] = {
            Ah + (size_t)brow * K + kofs, Al + (size_t)brow * K + kofs,
            Bh + (size_t)bcol * K + kofs, Bl + (size_t)bcol * K + kofs};
#pragma unroll
        for (int tile = 0; tile < 4; ++tile) {
            const bf16* base = srcs[tile];
            const uint32_t d = sb + tile * 8192;
            asm volatile("cp.async.cg.shared.global [%0], [%1], 16;"
                         :: "r"(d + so0), "l"(base + (size_t)row0 * K + c0 * 8));
            asm volatile("cp.async.cg.shared.global [%0], [%1], 16;"
                         :: "r"(d + so1), "l"(base + (size_t)row1 * K + c1 * 8));
        }
        asm volatile("cp.async.commit_group;" ::: "memory");
    };

    // ldmatrix address pieces (constant per thread across stages)
    const int arow_base = wm * 64 + (lane & 7) + ((lane >> 3) & 1) * 8;
    const int ach_half = lane >> 4;                       // 0/1
    const int brow_base = wn * 32 + ((lane >> 4) & 1) * 8 + (lane & 7);
    const int bch_half = (lane >> 3) & 1;                 // 0/1

    auto do_compute = [&](int buf) {
        const uint32_t sb = sbase + buf * 32768;
        const uint32_t Ahb = sb, Alb = sb + 8192;
        const uint32_t Bhb = sb + 16384, Blb = sb + 24576;
#pragma unroll
        for (int ks = 0; ks < 2; ++ks) {
            const int ach = ks * 2 + ach_half;
            const int bch = ks * 2 + bch_half;
            uint32_t a[4][4], bh[4][2], bl[4][2];
#pragma unroll
            for (int mi = 0; mi < 4; ++mi)
                LDSM4(a[mi], Ahb + swz(arow_base + mi * 16, ach));
#pragma unroll
            for (int p = 0; p < 2; ++p) {
                uint32_t r[4];
                LDSM4(r, Bhb + swz(brow_base + p * 16, bch));
                bh[p * 2][0] = r[0]; bh[p * 2][1] = r[1];
                bh[p * 2 + 1][0] = r[2]; bh[p * 2 + 1][1] = r[3];
            }
            // t0: Ah x Bh
#pragma unroll
            for (int mi = 0; mi < 4; ++mi)
#pragma unroll
                for (int ni = 0; ni < 4; ++ni)
                    MMA16(acc[mi][ni], a[mi], bh[ni][0], bh[ni][1]);
#pragma unroll
            for (int p = 0; p < 2; ++p) {
                uint32_t r[4];
                LDSM4(r, Blb + swz(brow_base + p * 16, bch));
                bl[p * 2][0] = r[0]; bl[p * 2][1] = r[1];
                bl[p * 2 + 1][0] = r[2]; bl[p * 2 + 1][1] = r[3];
            }
            // t1: Ah x Bl  (reuse a)
#pragma unroll
            for (int mi = 0; mi < 4; ++mi)
#pragma unroll
                for (int ni = 0; ni < 4; ++ni)
                    MMA16(acc[mi][ni], a[mi], bl[ni][0], bl[ni][1]);
            // Al fragments (overwrite a)
#pragma unroll
            for (int mi = 0; mi < 4; ++mi)
                LDSM4(a[mi], Alb + swz(arow_base + mi * 16, ach));
            // t2: Al x Bh  (reuse bh)
#pragma unroll
            for (int mi = 0; mi < 4; ++mi)
#pragma unroll
                for (int ni = 0; ni < 4; ++ni)
                    MMA16(acc[mi][ni], a[mi], bh[ni][0], bh[ni][1]);
        }
    };

    // 3-stage circular pipeline, loads run 2 stages ahead
    load_stage(0, 0);
    if (NST > 1) load_stage(1, 1);
    for (int s = 0; s < NST; ++s) {
        if (s + 1 < NST)
            asm volatile("cp.async.wait_group 1;" ::: "memory");
        else
            asm volatile("cp.async.wait_group 0;" ::: "memory");
        __syncthreads();
        if (s + 2 < NST) load_stage(s + 2, (s + 2) % 3);
        do_compute(s % 3);
    }

    // ---- epilogue ----
    if (DOTOUT) {
        float rs[4][2] = {};   // per (mi, h) partial row dots
#pragma unroll
        for (int mi = 0; mi < 4; ++mi) {
#pragma unroll
            for (int ni = 0; ni < 4; ++ni) {
                const int col = bcol + wn * 32 + ni * 8 + (lane & 3) * 2;
                const float2 bb = *(const float2*)&bias[col];
                const float2 wo = *(const float2*)&wout[col];
#pragma unroll
                for (int h = 0; h < 2; ++h) {
                    float v0 = acc[mi][ni][h * 2 + 0] + bb.x;
                    float v1 = acc[mi][ni][h * 2 + 1] + bb.y;
                    if (LEAKY) { v0 = leaky(v0); v1 = leaky(v1); }
                    rs[mi][h] += v0 * wo.x + v1 * wo.y;
                }
            }
        }
#pragma unroll
        for (int mi = 0; mi < 4; ++mi)
#pragma unroll
            for (int h = 0; h < 2; ++h) {
                rs[mi][h] += __shfl_xor_sync(0xFFFFFFFFu, rs[mi][h], 1);
                rs[mi][h] += __shfl_xor_sync(0xFFFFFFFFu, rs[mi][h], 2);
            }
        if ((lane & 3) == 0) {
            const int rbase = brow + wm * 64 + (lane >> 2);
#pragma unroll
            for (int mi = 0; mi < 4; ++mi)
#pragma unroll
                for (int h = 0; h < 2; ++h) {
                    const int r = rbase + mi * 16 + h * 8;
                    if (r < MREAL) atomicAdd(&dout[r], rs[mi][h]);
                }
        }
    } else {
#pragma unroll
        for (int mi = 0; mi < 4; ++mi) {
            const int r0 = brow + wm * 64 + mi * 16 + (lane >> 2);
#pragma unroll
            for (int ni = 0; ni < 4; ++ni) {
                const int col = bcol + wn * 32 + ni * 8 + (lane & 3) * 2;
                const float2 bb = *(const float2*)&bias[col];
#pragma unroll
                for (int h = 0; h < 2; ++h) {
                    const int r = r0 + h * 8;
                    float v0 = acc[mi][ni][h * 2 + 0] + bb.x;
                    float v1 = acc[mi][ni][h * 2 + 1] + bb.y;
                    if (LEAKY) { v0 = leaky(v0); v1 = leaky(v1); }
                    const __nv_bfloat162 hv = __floats2bfloat162_rn(v0, v1);
                    *(__nv_bfloat162*)&Ch[(size_t)r * NOUT + col] = hv;
                    const float l0 = v0 - __bfloat162float(hv.x);
                    const float l1 = v1 - __bfloat162float(hv.y);
                    *(__nv_bfloat162*)&Cl[(size_t)r * NOUT + col] =
                        __floats2bfloat162_rn(l0, l1);
                }
            }
        }
    }
}

// ---------------------------------------------------------------------------
// Prep (one kernel): W2/W3 transpose+split, out=b_out, head=-1, cnt=0
// ---------------------------------------------------------------------------
#define PW0 (HDIM * HDIM)
#define PW1 (2 * HDIM * HDIM)
__global__ void prep_all(const float* __restrict__ W2, const float* __restrict__ W3,
                         const float* __restrict__ bout, float* __restrict__ out,
                         int n) {
    const int g = blockIdx.x * blockDim.x + threadIdx.x;
    if (g >= PW1) {
        const int i = g - PW1;
        if (i < n) {
            out[i] = bout[0];
            g_head[i] = -1;
            g_cnt[i] = 0;
        }
        return;
    }
    const float* W; bf16 *Th, *Tl; int idx;
    if (g < PW0) { W = W2; Th = g_W2_h; Tl = g_W2_l; idx = g; }
    else         { W = W3; Th = g_W3_h; Tl = g_W3_l; idx = g - PW0; }
    const int n2 = idx / HDIM, k = idx % HDIM;
    const float v = W[(size_t)k * HDIM + n2];
    const bf16 h = __float2bfloat16(v);
    Th[idx] = h;
    Tl[idx] = __float2bfloat16(v - __bfloat162float(h));
}

// ---------------------------------------------------------------------------
// Wc = W_gcn @ W1 (blocks 0..127, k-row cached in smem) ; bc (block 128)
// ---------------------------------------------------------------------------
__global__ __launch_bounds__(256)
void wc_bc_kernel(const float* __restrict__ Wg, const float* __restrict__ W1,
                  const float* __restrict__ bg, const float* __restrict__ b1) {
    const int n = threadIdx.x;         // 0..255
    if (blockIdx.x == DIN) {           // bc = b_gcn @ W1 + b1
        float acc = b1[n];
#pragma unroll 8
        for (int j = 0; j < DGCN; ++j)
            acc += bg[j] * W1[(size_t)j * HDIM + n];
        g_bc[n] = acc;
        return;
    }
    __shared__ float row[DGCN];
    const int k = blockIdx.x;          // 0..127
    row[n] = Wg[(size_t)k * DGCN + n];
    row[n + 256] = Wg[(size_t)k * DGCN + n + 256];
    __syncthreads();
    float acc = 0.f;
#pragma unroll 8
    for (int j = 0; j < DGCN; ++j)
        acc += row[j] * W1[(size_t)j * HDIM + n];
    const bf16 h = __float2bfloat16(acc);
    g_Wc_h[n * DIN + k] = h;
    g_Wc_l[n * DIN + k] = __float2bfloat16(acc - __bfloat162float(h));
}

// ---------------------------------------------------------------------------
// Linked-list bucket scatter: link[e] = old head of dst[e]; cnt[dst]++.
// ---------------------------------------------------------------------------
__global__ void scatter_ll(const int* __restrict__ src,
                           const int* __restrict__ dst, int E, int n) {
    int e = blockIdx.x * blockDim.x + threadIdx.x;
    if (e < E) {
        int d = dst[e], s = src[e];
        if ((unsigned)d >= (unsigned)n || (unsigned)s >= (unsigned)n) return;
        atomicAdd(&g_cnt[d], 1);
        g_link[e] = atomicExch(&g_head[d], e);
    }
}

// ---------------------------------------------------------------------------
// xs = S @ x: warp per node walking its bucket list; lane = 4 cols (float4).
// dinv computed inline from cnt. Split bf16 output.
// ---------------------------------------------------------------------------
__global__ __launch_bounds__(256)
void agg_warp_kernel(const float* __restrict__ x, const int* __restrict__ src,
                     int n) {
    const int node = (blockIdx.x * blockDim.x + threadIdx.x) >> 5;
    if (node >= n) return;
    const int lane = threadIdx.x & 31;
    const float di = rsqrtf(1.0f + (float)g_cnt[node]);
    float4 v = *(const float4*)&x[(size_t)node * DIN + lane * 4];
    float a0 = di * v.x, a1 = di * v.y, a2 = di * v.z, a3 = di * v.w;
    int e = g_head[node];
    while (e >= 0) {
        const int s = src[e];
        const int nx = g_link[e];
        const float ds = rsqrtf(1.0f + (float)g_cnt[s]);
        const float4 u = *(const float4*)&x[(size_t)s * DIN + lane * 4];
        a0 += ds * u.x; a1 += ds * u.y; a2 += ds * u.z; a3 += ds * u.w;
        e = nx;
    }
    a0 *= di; a1 *= di; a2 *= di; a3 *= di;
    const size_t idx = (size_t)node * DIN + lane * 4;
    const __nv_bfloat162 h01 = __floats2bfloat162_rn(a0, a1);
    const __nv_bfloat162 h23 = __floats2bfloat162_rn(a2, a3);
    *(__nv_bfloat162*)&g_xs_h[idx] = h01;
    *(__nv_bfloat162*)&g_xs_h[idx + 2] = h23;
    *(__nv_bfloat162*)&g_xs_l[idx] = __floats2bfloat162_rn(
        a0 - __bfloat162float(h01.x), a1 - __bfloat162float(h01.y));
    *(__nv_bfloat162*)&g_xs_l[idx + 2] = __floats2bfloat162_rn(
        a2 - __bfloat162float(h23.x), a3 - __bfloat162float(h23.y));
}

// ---------------------------------------------------------------------------
// Launch  (6 launches before GEMM2 -> ncu -s 5 -c 1 profiles GEMM2)
// ---------------------------------------------------------------------------
extern "C" void kernel_launch(void* const* d_in, const int* in_sizes, int n_in,
                              void* d_out, int out_size) {
    const float* x     = (const float*)d_in[0];
    const int*   ei    = (const int*)d_in[1];
    const float* W_gcn = (const float*)d_in[2];
    const float* b_gcn = (const float*)d_in[3];
    const float* W1    = (const float*)d_in[4];
    const float* b1    = (const float*)d_in[5];
    const float* W2    = (const float*)d_in[6];
    const float* b2    = (const float*)d_in[7];
    const float* W3    = (const float*)d_in[8];
    const float* b3    = (const float*)d_in[9];
    const float* Wout  = (const float*)d_in[10];
    const float* bout  = (const float*)d_in[11];
    float* out = (float*)d_out;

    const int N = in_sizes[0] / DIN;
    const int E = in_sizes[1] / 2;
    const int* src = ei;
    const int* dst = ei + E;

    bf16 *p_xs_h, *p_xs_l, *p_h1_h, *p_h1_l, *p_h2_h, *p_h2_l;
    bf16 *p_Wc_h, *p_Wc_l, *p_W2_h, *p_W2_l, *p_W3_h, *p_W3_l;
    float* p_bc;
    cudaGetSymbolAddress((void**)&p_xs_h, g_xs_h);
    cudaGetSymbolAddress((void**)&p_xs_l, g_xs_l);
    cudaGetSymbolAddress((void**)&p_h1_h, g_h1_h);
    cudaGetSymbolAddress((void**)&p_h1_l, g_h1_l);
    cudaGetSymbolAddress((void**)&p_h2_h, g_h2_h);
    cudaGetSymbolAddress((void**)&p_h2_l, g_h2_l);
    cudaGetSymbolAddress((void**)&p_Wc_h, g_Wc_h);
    cudaGetSymbolAddress((void**)&p_Wc_l, g_Wc_l);
    cudaGetSymbolAddress((void**)&p_W2_h, g_W2_h);
    cudaGetSymbolAddress((void**)&p_W2_l, g_W2_l);
    cudaGetSymbolAddress((void**)&p_W3_h, g_W3_h);
    cudaGetSymbolAddress((void**)&p_W3_l, g_W3_l);
    cudaGetSymbolAddress((void**)&p_bc, g_bc);

    const int SMEM = 98304;  // 3 stages x 32KB
    cudaFuncSetAttribute(mma_gemm<128, true, false>,
                         cudaFuncAttributeMaxDynamicSharedMemorySize, SMEM);
    cudaFuncSetAttribute(mma_gemm<256, true, false>,
                         cudaFuncAttributeMaxDynamicSharedMemorySize, SMEM);
    cudaFuncSetAttribute(mma_gemm<256, true, true>,
                         cudaFuncAttributeMaxDynamicSharedMemorySize, SMEM);

    // 1) prep: W2/W3 split + out=b_out + head=-1 + cnt=0
    prep_all<<<DIV_UP(PW1 + N, 256), 256>>>(W2, W3, bout, out, N);
    // 2) Wc = W_gcn@W1 (+bc)
    wc_bc_kernel<<<DIN + 1, 256>>>(W_gcn, W1, b_gcn, b1);
    // 3) bucket lists + degree counts
    scatter_ll<<<DIV_UP(E, 256), 256>>>(src, dst, E, N);
    // 4) xs = S @ x  (split bf16 output), warp per node
    agg_warp_kernel<<<DIV_UP(N * 32, 256), 256>>>(x, src, N);

    const int mt = DIV_UP(N, 128);
    const dim3 grid(HDIM / 128, mt);
    // 5) h1 = leaky(xs @ Wc + bc)
    mma_gemm<128, true, false><<<grid, 256, SMEM>>>(
        p_xs_h, p_xs_l, p_Wc_h, p_Wc_l, p_bc, p_h1_h, p_h1_l,
        nullptr, nullptr, HDIM, N);
    // 6) h2 = leaky(h1 @ W2 + b2)   <- profiled by ncu (-s 5 -c 1)
    mma_gemm<256, true, false><<<grid, 256, SMEM>>>(
        p_h1_h, p_h1_l, p_W2_h, p_W2_l, b2, p_h2_h, p_h2_l,
        nullptr, nullptr, HDIM, N);
    // 7) out += leaky(h2 @ W3 + b3) . Wout   (fused)
    mma_gemm<256, true, true><<<grid, 256, SMEM>>>(
        p_h2_h, p_h2_l, p_W3_h, p_W3_l, b3, nullptr, nullptr,
        Wout, out, HDIM, N);
}